// round 10
// baseline (speedup 1.0000x reference)
#include <cuda_runtime.h>
#include <cuda_bf16.h>
#include <math.h>

// ---------------- problem constants ----------------
#define NN 50000
#define EE 800000
#define F_IN 512
#define H1 8
#define F_HID 8
#define O1 64          // H1*F_HID
#define NLAB 64
#define LRELU 0.2f

#define FULLM 0xffffffffu

// ---------------- device scratch (no allocs allowed) ----------------
__device__ ulonglong2 g_Wp[(F_IN / 2) * 32];   // W1 packed: [kpair][lane] -> {(o=2l),(o=2l+1)} f32x2
__device__ ulonglong2 g_W2p[(O1 / 2) * 32];    // W2 packed same format
__device__ float g_Wh1[(size_t)NN * O1];       // layer-1 node features
__device__ float g_es1[NN * H1];
__device__ float g_ed1[NN * H1];
__device__ float g_h1[(size_t)NN * O1];        // post-aggregation, post-ELU
__device__ float g_Wh2[(size_t)NN * NLAB];
__device__ float g_es2[NN];
__device__ float g_ed2[NN];
__device__ int   g_cnt[NN];                    // zero at entry (re-zeroed at tail of k5)
__device__ int   g_rank[EE];
__device__ int   g_off[NN + 1];
__device__ int   g_ssrc[EE + 64];              // +pad (zero-init) for unguarded pipelined loads

// ---------------- f32x2 helpers (dense GEMMs only) ----------------
__device__ __forceinline__ unsigned long long pack2(float lo, float hi) {
    unsigned long long r;
    asm("mov.b64 %0, {%1, %2};" : "=l"(r) : "f"(lo), "f"(hi));
    return r;
}
__device__ __forceinline__ void fma2(unsigned long long& acc, unsigned long long a,
                                     unsigned long long b) {
    asm("fma.rn.f32x2 %0, %1, %2, %0;" : "+l"(acc) : "l"(a), "l"(b));
}
__device__ __forceinline__ float2 unpack2(unsigned long long v) {
    float lo, hi;
    asm("mov.b64 {%0, %1}, %2;" : "=f"(lo), "=f"(hi) : "l"(v));
    return make_float2(lo, hi);
}

__device__ __forceinline__ float lrelu_f(float v) { return fmaxf(v, LRELU * v); }
__device__ __forceinline__ float elu_f(float v)   { return v > 0.f ? v : __expf(v) - 1.f; }

// ============ K1: pack W1 (32 blk) + pack W2 (4 blk) + hist (rank-storing) ============
#define HIST_BLKS ((EE + 255) / 256)
__global__ __launch_bounds__(256) void k1_prep_hist(const float* __restrict__ W1,
                                                    const float* __restrict__ W2,
                                                    const int* __restrict__ dst) {
    const int bid = blockIdx.x;
    const int tid = threadIdx.x;
    if (bid < 32) {
        int i = bid * 256 + tid;   // < 8192 = (F_IN/2)*32
        int p = i >> 5, l = i & 31;
        int o0 = 2 * l, o1 = 2 * l + 1;
        int k0 = 2 * p, k1 = 2 * p + 1;
        // W1: [H1, F_IN, F_HID]; element (k,o) at (o>>3)*4096 + k*8 + (o&7)
        float w00 = W1[(o0 >> 3) * (F_IN * F_HID) + k0 * F_HID + (o0 & 7)];
        float w10 = W1[(o0 >> 3) * (F_IN * F_HID) + k1 * F_HID + (o0 & 7)];
        float w01 = W1[(o1 >> 3) * (F_IN * F_HID) + k0 * F_HID + (o1 & 7)];
        float w11 = W1[(o1 >> 3) * (F_IN * F_HID) + k1 * F_HID + (o1 & 7)];
        ulonglong2 v;
        v.x = pack2(w00, w10);
        v.y = pack2(w01, w11);
        g_Wp[i] = v;
    } else if (bid < 36) {
        int i = (bid - 32) * 256 + tid;   // < 1024 = (O1/2)*32
        int p = i >> 5, l = i & 31;
        int o0 = 2 * l, o1 = 2 * l + 1;
        int k0 = 2 * p, k1 = 2 * p + 1;
        // W2: [1, O1, NLAB]; element (k,o) at k*64 + o
        ulonglong2 v;
        v.x = pack2(W2[k0 * NLAB + o0], W2[k1 * NLAB + o0]);
        v.y = pack2(W2[k0 * NLAB + o1], W2[k1 * NLAB + o1]);
        g_W2p[i] = v;
    } else {
        int e = (bid - 36) * 256 + tid;
        if (e < EE) g_rank[e] = atomicAdd(&g_cnt[dst[e]], 1);
    }
}

// ================= K2: gemm1 (blocks 1..) + scan (block 0) =================
#define G1_NB 64
#define G1_KC 128
__global__ __launch_bounds__(256) void k2_gemm1_scan(const float* __restrict__ x,
                                                     const float* __restrict__ a1s,
                                                     const float* __restrict__ a1d) {
    __shared__ float xs[G1_NB][G1_KC];   // 32KB (scan block reuses a corner)
    const int tid = threadIdx.x;

    if (blockIdx.x == 0) {
        // ---- exclusive scan of g_cnt -> g_off (256 threads) ----
        int* ssum = (int*)xs;
        const int CH = (NN + 255) / 256;   // 196
        int b = tid * CH;
        int e2 = b + CH; if (e2 > NN) e2 = NN;
        int s = 0;
        for (int i = b; i < e2; i++) s += g_cnt[i];
        ssum[tid] = s;
        __syncthreads();
        for (int d = 1; d < 256; d <<= 1) {
            int v = (tid >= d) ? ssum[tid - d] : 0;
            __syncthreads();
            ssum[tid] += v;
            __syncthreads();
        }
        int off = (tid == 0) ? 0 : ssum[tid - 1];
        for (int i = b; i < e2; i++) {
            g_off[i] = off;
            off += g_cnt[i];
        }
        if (tid == 255) g_off[NN] = ssum[255];
        return;
    }

    // ---- gemm1: Wh1 = x @ W1 (+ es1/ed1 epilogue), f32x2 ----
    const int lane = tid & 31;
    const int w = tid >> 5;
    const int nb0 = (blockIdx.x - 1) * G1_NB;

    unsigned long long acc[8][2];
#pragma unroll
    for (int n = 0; n < 8; n++) { acc[n][0] = 0ull; acc[n][1] = 0ull; }

    for (int kt = 0; kt < F_IN; kt += G1_KC) {
        __syncthreads();
        for (int idx = tid; idx < G1_NB * (G1_KC / 4); idx += 256) {
            int n = idx >> 5;
            int c = idx & 31;
            int g = nb0 + n;
            float4 v = make_float4(0.f, 0.f, 0.f, 0.f);
            if (g < NN) v = *(const float4*)&x[(size_t)g * F_IN + kt + c * 4];
            *(float4*)&xs[n][c * 4] = v;
        }
        __syncthreads();

        const int nrow = w * 8;
        const int pbase = kt >> 1;
#pragma unroll 4
        for (int q = 0; q < G1_KC / 2; q += 2) {
            ulonglong2 wA = g_Wp[(pbase + q) * 32 + lane];
            ulonglong2 wB = g_Wp[(pbase + q + 1) * 32 + lane];
#pragma unroll
            for (int n = 0; n < 8; n++) {
                ulonglong2 xv = *(const ulonglong2*)&xs[nrow + n][2 * q];
                fma2(acc[n][0], xv.x, wA.x);
                fma2(acc[n][1], xv.x, wA.y);
                fma2(acc[n][0], xv.y, wB.x);
                fma2(acc[n][1], xv.y, wB.y);
            }
        }
    }

    const float as0 = a1s[2 * lane], as1 = a1s[2 * lane + 1];
    const float ad0 = a1d[2 * lane], ad1 = a1d[2 * lane + 1];
#pragma unroll
    for (int n = 0; n < 8; n++) {
        int g = nb0 + w * 8 + n;
        if (g >= NN) continue;  // uniform across warp
        float2 p0 = unpack2(acc[n][0]);
        float2 p1 = unpack2(acc[n][1]);
        float o0 = p0.x + p0.y;
        float o1 = p1.x + p1.y;
        *(float2*)&g_Wh1[(size_t)g * O1 + 2 * lane] = make_float2(o0, o1);
        float ps = o0 * as0 + o1 * as1;
        float pd = o0 * ad0 + o1 * ad1;
        ps += __shfl_xor_sync(FULLM, ps, 1);
        ps += __shfl_xor_sync(FULLM, ps, 2);
        pd += __shfl_xor_sync(FULLM, pd, 1);
        pd += __shfl_xor_sync(FULLM, pd, 2);
        if ((lane & 3) == 0) {
            g_es1[g * H1 + (lane >> 2)] = ps;
            g_ed1[g * H1 + (lane >> 2)] = pd;
        }
    }
}

// ================= K3: pure scatter (atomic-free, rank-based) =================
__global__ void k3_scatter(const int* __restrict__ src, const int* __restrict__ dst) {
    int e = blockIdx.x * blockDim.x + threadIdx.x;
    if (e < EE) g_ssrc[g_off[dst[e]] + g_rank[e]] = src[e];
}

// ====== K4: layer-1 aggregate, 2 warps/node, batch-8, inline p, scalar FFMA ======
__global__ __launch_bounds__(256) void k4_agg1() {
    __shared__ float2 sacc[4][32];
    __shared__ float  ssumh[4][32];
    const int tid  = threadIdx.x;
    const int lane = tid & 31;
    const int w    = tid >> 5;
    const int half = w & 1;
    const int pair = w >> 1;                 // 0..3
    const int node = blockIdx.x * 4 + pair;
    const int srcg = lane & 0x1C;            // (h<<2): shfl source group base
    const int e4   = lane & 3;
    const int e8   = lane & 7;
    const int h    = lane >> 2;

    float sumP = 0.f;
    float2 acc0 = make_float2(0.f, 0.f), acc1 = make_float2(0.f, 0.f);

    if (node < NN) {
        const int beg = g_off[node], end = g_off[node + 1];
        const float edh = g_ed1[node * H1 + h];
        const int start = beg + half * 8;    // interleaved 8-edge chunks per warp
        if (start < end) {
            int   s_l = g_ssrc[start + e8];
            int   sA  = __shfl_sync(FULLM, s_l, e4);
            int   sB  = __shfl_sync(FULLM, s_l, 4 + e4);
            float esA = g_es1[sA * H1 + h];
            float esB = g_es1[sB * H1 + h];
            for (int base = start; base < end; base += 16) {
                // prefetch next chunk (pads make loads safe; garbage masked by m)
                int   s_n  = g_ssrc[base + 16 + e8];
                int   sAn  = __shfl_sync(FULLM, s_n, e4);
                int   sBn  = __shfl_sync(FULLM, s_n, 4 + e4);
                float esAn = g_es1[sAn * H1 + h];
                float esBn = g_es1[sBn * H1 + h];

                const int m = end - base;
                float pA = (e4 < m)     ? __expf(lrelu_f(esA + edh)) : 0.f;
                float pB = (4 + e4 < m) ? __expf(lrelu_f(esB + edh)) : 0.f;
                sumP += pA + pB;
#pragma unroll
                for (int j = 0; j < 8; j++) {
                    int s   = __shfl_sync(FULLM, s_l, j);
                    float p = __shfl_sync(FULLM, (j < 4) ? pA : pB, srcg | (j & 3));
                    float2 wv = *(const float2*)&g_Wh1[(size_t)s * O1 + 2 * lane];
                    if (j & 1) { acc1.x += p * wv.x; acc1.y += p * wv.y; }
                    else       { acc0.x += p * wv.x; acc0.y += p * wv.y; }
                }
                s_l = s_n; esA = esAn; esB = esBn;
            }
        }
    }
    // per-head partial: 4 lanes of group h cover this warp's edges
    sumP += __shfl_xor_sync(FULLM, sumP, 1);
    sumP += __shfl_xor_sync(FULLM, sumP, 2);
    float2 acc = make_float2(acc0.x + acc1.x, acc0.y + acc1.y);

    if (half) {
        sacc[pair][lane]  = acc;
        ssumh[pair][lane] = sumP;
    }
    __syncthreads();
    if (!half && node < NN) {
        float2 o = sacc[pair][lane];
        float st = sumP + ssumh[pair][lane];
        acc.x += o.x; acc.y += o.y;
        const float inv = 1.f / (st + 1e-10f);
        *(float2*)&g_h1[(size_t)node * O1 + 2 * lane] =
            make_float2(elu_f(acc.x * inv), elu_f(acc.y * inv));
    }
}

// ========= K4c: GEMM2 (batched, W2 packed, f32x2) + es2/ed2 epilogue =========
#define G2_NB 64
__global__ __launch_bounds__(256) void k4c_gemm2(const float* __restrict__ a2s,
                                                 const float* __restrict__ a2d) {
    __shared__ float hs[G2_NB][O1];   // 16KB
    const int tid = threadIdx.x;
    const int lane = tid & 31;
    const int w = tid >> 5;
    const int nb0 = blockIdx.x * G2_NB;

    for (int idx = tid; idx < G2_NB * (O1 / 4); idx += 256) {
        int n = idx >> 4;
        int c = idx & 15;
        int g = nb0 + n;
        float4 v = make_float4(0.f, 0.f, 0.f, 0.f);
        if (g < NN) v = *(const float4*)&g_h1[(size_t)g * O1 + c * 4];
        *(float4*)&hs[n][c * 4] = v;
    }
    __syncthreads();

    unsigned long long acc[8][2];
#pragma unroll
    for (int n = 0; n < 8; n++) { acc[n][0] = 0ull; acc[n][1] = 0ull; }

    const int nrow = w * 8;
#pragma unroll 4
    for (int q = 0; q < O1 / 2; q += 2) {
        ulonglong2 wA = g_W2p[q * 32 + lane];
        ulonglong2 wB = g_W2p[(q + 1) * 32 + lane];
#pragma unroll
        for (int n = 0; n < 8; n++) {
            ulonglong2 xv = *(const ulonglong2*)&hs[nrow + n][2 * q];
            fma2(acc[n][0], xv.x, wA.x);
            fma2(acc[n][1], xv.x, wA.y);
            fma2(acc[n][0], xv.y, wB.x);
            fma2(acc[n][1], xv.y, wB.y);
        }
    }

    const float as0 = a2s[2 * lane], as1 = a2s[2 * lane + 1];
    const float ad0 = a2d[2 * lane], ad1 = a2d[2 * lane + 1];
#pragma unroll
    for (int n = 0; n < 8; n++) {
        int g = nb0 + w * 8 + n;
        if (g >= NN) continue;  // uniform across warp
        float2 p0 = unpack2(acc[n][0]);
        float2 p1 = unpack2(acc[n][1]);
        float o0 = p0.x + p0.y;
        float o1 = p1.x + p1.y;
        *(float2*)&g_Wh2[(size_t)g * NLAB + 2 * lane] = make_float2(o0, o1);
        float ps = o0 * as0 + o1 * as1;
        float pd = o0 * ad0 + o1 * ad1;
#pragma unroll
        for (int o = 16; o; o >>= 1) {
            ps += __shfl_xor_sync(FULLM, ps, o);
            pd += __shfl_xor_sync(FULLM, pd, o);
        }
        if (lane == 0) { g_es2[g] = ps; g_ed2[g] = pd; }
    }
}

// ====== K5: layer-2 aggregate, 2 warps/node + pipelined gather + softmax ======
__global__ __launch_bounds__(256) void k5_agg2(float* __restrict__ out) {
    __shared__ float2 sacc[4][32];
    __shared__ float  ssum[4];
    const int tid  = threadIdx.x;
    const int lane = tid & 31;
    const int w    = tid >> 5;
    const int half = w & 1;
    const int pair = w >> 1;
    const int node = blockIdx.x * 4 + pair;
    const int e8   = lane & 7;

    int gid = blockIdx.x * blockDim.x + tid;
    if (gid < NN) g_cnt[gid] = 0;   // leave cnt zeroed for the next call

    float sumP = 0.f;
    float2 acc0 = make_float2(0.f, 0.f), acc1 = make_float2(0.f, 0.f);

    if (node < NN) {
        const int beg = g_off[node], end = g_off[node + 1];
        const float ed = g_ed2[node];
        const int start = beg + half * 8;
        if (start < end) {
            int   s_l = g_ssrc[start + e8];
            float v_l = g_es2[s_l];
            for (int base = start; base < end; base += 16) {
                int   s_n = g_ssrc[base + 16 + e8];
                float v_n = g_es2[s_n];

                const int m = end - base;
                float p_l = (e8 < m) ? __expf(lrelu_f(v_l + ed)) : 0.f;
                if (lane < 8) sumP += p_l;   // lanes 8-31 hold duplicates
#pragma unroll
                for (int j = 0; j < 8; j++) {
                    int s   = __shfl_sync(FULLM, s_l, j);
                    float p = __shfl_sync(FULLM, p_l, j);
                    float2 wv = *(const float2*)&g_Wh2[(size_t)s * NLAB + 2 * lane];
                    if (j & 1) { acc1.x += p * wv.x; acc1.y += p * wv.y; }
                    else       { acc0.x += p * wv.x; acc0.y += p * wv.y; }
                }
                s_l = s_n; v_l = v_n;
            }
        }
    }
#pragma unroll
    for (int o = 16; o; o >>= 1) sumP += __shfl_xor_sync(FULLM, sumP, o);
    float2 acc = make_float2(acc0.x + acc1.x, acc0.y + acc1.y);

    if (half) {
        sacc[pair][lane] = acc;
        if (lane == 0) ssum[pair] = sumP;
    }
    __syncthreads();
    if (!half && node < NN) {
        float2 o = sacc[pair][lane];
        float st = sumP + ssum[pair];
        acc.x += o.x; acc.y += o.y;

        const float inv = 1.f / (st + 1e-10f);
        float o0 = acc.x * inv;
        float o1 = acc.y * inv;

        // head-mean is identity (H2=1); fused softmax over 64 classes
        float m2 = fmaxf(o0, o1);
#pragma unroll
        for (int o2 = 16; o2; o2 >>= 1) m2 = fmaxf(m2, __shfl_xor_sync(FULLM, m2, o2));
        float e0 = __expf(o0 - m2);
        float e1 = __expf(o1 - m2);
        float s2 = e0 + e1;
#pragma unroll
        for (int o2 = 16; o2; o2 >>= 1) s2 += __shfl_xor_sync(FULLM, s2, o2);
        float r = 1.f / s2;
        *(float2*)&out[(size_t)node * NLAB + 2 * lane] = make_float2(e0 * r, e1 * r);
    }
}

// ---------------- launch ----------------
extern "C" void kernel_launch(void* const* d_in, const int* in_sizes, int n_in,
                              void* d_out, int out_size) {
    const float* x    = (const float*)d_in[0];
    const float* W1   = (const float*)d_in[1];
    const float* a1s  = (const float*)d_in[2];
    const float* a1d  = (const float*)d_in[3];
    const float* W2   = (const float*)d_in[4];
    const float* a2s  = (const float*)d_in[5];
    const float* a2d  = (const float*)d_in[6];
    const int*   src  = (const int*)d_in[7];
    const int*   dst  = (const int*)d_in[8];
    float* out = (float*)d_out;

    k1_prep_hist<<<36 + HIST_BLKS, 256>>>(W1, W2, dst);
    k2_gemm1_scan<<<1 + (NN + G1_NB - 1) / G1_NB, 256>>>(x, a1s, a1d);
    k3_scatter<<<HIST_BLKS, 256>>>(src, dst);
    k4_agg1<<<(NN + 3) / 4, 256>>>();
    k4c_gemm2<<<(NN + G2_NB - 1) / G2_NB, 256>>>(a2s, a2d);
    k5_agg2<<<(NN + 3) / 4, 256>>>(out);
}

// round 11
// speedup vs baseline: 1.1111x; 1.1111x over previous
#include <cuda_runtime.h>
#include <cuda_bf16.h>
#include <math.h>

// ---------------- problem constants ----------------
#define NN 50000
#define EE 800000
#define F_IN 512
#define H1 8
#define F_HID 8
#define O1 64          // H1*F_HID
#define NLAB 64
#define LRELU 0.2f

#define FULLM 0xffffffffu

// ---------------- device scratch (no allocs allowed) ----------------
__device__ ulonglong2 g_Wp[(F_IN / 2) * 32];   // W1 packed: [kpair][lane] -> {(o=2l),(o=2l+1)} f32x2
__device__ ulonglong2 g_W2p[(O1 / 2) * 32];    // W2 packed same format
__device__ float g_Wh1[(size_t)NN * O1];       // layer-1 node features
__device__ float g_es1[NN * H1];
__device__ float g_ed1[NN * H1];
__device__ float g_h1[(size_t)NN * O1];        // post-aggregation, post-ELU
__device__ float g_Wh2[(size_t)NN * NLAB];
__device__ float g_es2[NN];
__device__ float g_ed2[NN];
__device__ int   g_cnt[NN];                    // zero at entry (re-zeroed at tail of k5)
__device__ int   g_rank[EE];
__device__ int   g_off[NN + 1];
__device__ int   g_ssrc[EE + 64];              // +pad (zero-init) for unguarded pipelined loads

// ---------------- f32x2 helpers (dense GEMMs only) ----------------
__device__ __forceinline__ unsigned long long pack2(float lo, float hi) {
    unsigned long long r;
    asm("mov.b64 %0, {%1, %2};" : "=l"(r) : "f"(lo), "f"(hi));
    return r;
}
__device__ __forceinline__ void fma2(unsigned long long& acc, unsigned long long a,
                                     unsigned long long b) {
    asm("fma.rn.f32x2 %0, %1, %2, %0;" : "+l"(acc) : "l"(a), "l"(b));
}
__device__ __forceinline__ float2 unpack2(unsigned long long v) {
    float lo, hi;
    asm("mov.b64 {%0, %1}, %2;" : "=f"(lo), "=f"(hi) : "l"(v));
    return make_float2(lo, hi);
}

__device__ __forceinline__ float lrelu_f(float v) { return fmaxf(v, LRELU * v); }
__device__ __forceinline__ float elu_f(float v)   { return v > 0.f ? v : __expf(v) - 1.f; }

// ============ K1: pack W1 (32 blk) + pack W2 (4 blk) + hist ×4 vectorized ============
#define HIST4_BLKS ((EE + 1023) / 1024)
__global__ __launch_bounds__(256) void k1_prep_hist(const float* __restrict__ W1,
                                                    const float* __restrict__ W2,
                                                    const int* __restrict__ dst) {
    const int bid = blockIdx.x;
    const int tid = threadIdx.x;
    if (bid < 32) {
        int i = bid * 256 + tid;   // < 8192 = (F_IN/2)*32
        int p = i >> 5, l = i & 31;
        int o0 = 2 * l, o1 = 2 * l + 1;
        int k0 = 2 * p, k1 = 2 * p + 1;
        // W1: [H1, F_IN, F_HID]; element (k,o) at (o>>3)*4096 + k*8 + (o&7)
        float w00 = W1[(o0 >> 3) * (F_IN * F_HID) + k0 * F_HID + (o0 & 7)];
        float w10 = W1[(o0 >> 3) * (F_IN * F_HID) + k1 * F_HID + (o0 & 7)];
        float w01 = W1[(o1 >> 3) * (F_IN * F_HID) + k0 * F_HID + (o1 & 7)];
        float w11 = W1[(o1 >> 3) * (F_IN * F_HID) + k1 * F_HID + (o1 & 7)];
        ulonglong2 v;
        v.x = pack2(w00, w10);
        v.y = pack2(w01, w11);
        g_Wp[i] = v;
    } else if (bid < 36) {
        int i = (bid - 32) * 256 + tid;   // < 1024 = (O1/2)*32
        int p = i >> 5, l = i & 31;
        int o0 = 2 * l, o1 = 2 * l + 1;
        int k0 = 2 * p, k1 = 2 * p + 1;
        // W2: [1, O1, NLAB]; element (k,o) at k*64 + o
        ulonglong2 v;
        v.x = pack2(W2[k0 * NLAB + o0], W2[k1 * NLAB + o0]);
        v.y = pack2(W2[k0 * NLAB + o1], W2[k1 * NLAB + o1]);
        g_W2p[i] = v;
    } else {
        int e = (bid - 36) * 1024 + tid * 4;
        if (e + 3 < EE) {
            int4 d4 = *(const int4*)&dst[e];
            int4 r4;
            r4.x = atomicAdd(&g_cnt[d4.x], 1);
            r4.y = atomicAdd(&g_cnt[d4.y], 1);
            r4.z = atomicAdd(&g_cnt[d4.z], 1);
            r4.w = atomicAdd(&g_cnt[d4.w], 1);
            *(int4*)&g_rank[e] = r4;
        } else {
            for (int q = e; q < EE; q++) g_rank[q] = atomicAdd(&g_cnt[dst[q]], 1);
        }
    }
}

// ================= K2: gemm1 (blocks 1..) + scan (block 0) =================
#define G1_NB 64
#define G1_KC 128
__global__ __launch_bounds__(256) void k2_gemm1_scan(const float* __restrict__ x,
                                                     const float* __restrict__ a1s,
                                                     const float* __restrict__ a1d) {
    __shared__ float xs[G1_NB][G1_KC];   // 32KB (scan block reuses a corner)
    const int tid = threadIdx.x;

    if (blockIdx.x == 0) {
        // ---- exclusive scan of g_cnt -> g_off (256 threads) ----
        int* ssum = (int*)xs;
        const int CH = (NN + 255) / 256;   // 196
        int b = tid * CH;
        int e2 = b + CH; if (e2 > NN) e2 = NN;
        int s = 0;
        for (int i = b; i < e2; i++) s += g_cnt[i];
        ssum[tid] = s;
        __syncthreads();
        for (int d = 1; d < 256; d <<= 1) {
            int v = (tid >= d) ? ssum[tid - d] : 0;
            __syncthreads();
            ssum[tid] += v;
            __syncthreads();
        }
        int off = (tid == 0) ? 0 : ssum[tid - 1];
        for (int i = b; i < e2; i++) {
            g_off[i] = off;
            off += g_cnt[i];
        }
        if (tid == 255) g_off[NN] = ssum[255];
        return;
    }

    // ---- gemm1: Wh1 = x @ W1 (+ es1/ed1 epilogue), f32x2 ----
    const int lane = tid & 31;
    const int w = tid >> 5;
    const int nb0 = (blockIdx.x - 1) * G1_NB;

    unsigned long long acc[8][2];
#pragma unroll
    for (int n = 0; n < 8; n++) { acc[n][0] = 0ull; acc[n][1] = 0ull; }

    for (int kt = 0; kt < F_IN; kt += G1_KC) {
        __syncthreads();
        for (int idx = tid; idx < G1_NB * (G1_KC / 4); idx += 256) {
            int n = idx >> 5;
            int c = idx & 31;
            int g = nb0 + n;
            float4 v = make_float4(0.f, 0.f, 0.f, 0.f);
            if (g < NN) v = *(const float4*)&x[(size_t)g * F_IN + kt + c * 4];
            *(float4*)&xs[n][c * 4] = v;
        }
        __syncthreads();

        const int nrow = w * 8;
        const int pbase = kt >> 1;
#pragma unroll 4
        for (int q = 0; q < G1_KC / 2; q += 2) {
            ulonglong2 wA = g_Wp[(pbase + q) * 32 + lane];
            ulonglong2 wB = g_Wp[(pbase + q + 1) * 32 + lane];
#pragma unroll
            for (int n = 0; n < 8; n++) {
                ulonglong2 xv = *(const ulonglong2*)&xs[nrow + n][2 * q];
                fma2(acc[n][0], xv.x, wA.x);
                fma2(acc[n][1], xv.x, wA.y);
                fma2(acc[n][0], xv.y, wB.x);
                fma2(acc[n][1], xv.y, wB.y);
            }
        }
    }

    const float as0 = a1s[2 * lane], as1 = a1s[2 * lane + 1];
    const float ad0 = a1d[2 * lane], ad1 = a1d[2 * lane + 1];
#pragma unroll
    for (int n = 0; n < 8; n++) {
        int g = nb0 + w * 8 + n;
        if (g >= NN) continue;  // uniform across warp
        float2 p0 = unpack2(acc[n][0]);
        float2 p1 = unpack2(acc[n][1]);
        float o0 = p0.x + p0.y;
        float o1 = p1.x + p1.y;
        *(float2*)&g_Wh1[g * O1 + 2 * lane] = make_float2(o0, o1);
        float ps = o0 * as0 + o1 * as1;
        float pd = o0 * ad0 + o1 * ad1;
        ps += __shfl_xor_sync(FULLM, ps, 1);
        ps += __shfl_xor_sync(FULLM, ps, 2);
        pd += __shfl_xor_sync(FULLM, pd, 1);
        pd += __shfl_xor_sync(FULLM, pd, 2);
        if ((lane & 3) == 0) {
            g_es1[g * H1 + (lane >> 2)] = ps;
            g_ed1[g * H1 + (lane >> 2)] = pd;
        }
    }
}

// ============ K3: pure scatter (atomic-free, rank-based), ×4 vectorized ============
__global__ void k3_scatter(const int* __restrict__ src, const int* __restrict__ dst) {
    int e = (blockIdx.x * blockDim.x + threadIdx.x) * 4;
    if (e + 3 < EE) {
        int4 d4 = *(const int4*)&dst[e];
        int4 s4 = *(const int4*)&src[e];
        int4 r4 = *(const int4*)&g_rank[e];
        g_ssrc[g_off[d4.x] + r4.x] = s4.x;
        g_ssrc[g_off[d4.y] + r4.y] = s4.y;
        g_ssrc[g_off[d4.z] + r4.z] = s4.z;
        g_ssrc[g_off[d4.w] + r4.w] = s4.w;
    } else {
        for (int q = e; q < EE; q++) g_ssrc[g_off[dst[q]] + g_rank[q]] = src[q];
    }
}

// ====== K4: layer-1 aggregate, batch-8, inline p (pipelined es1 gather) + ELU ======
__global__ __launch_bounds__(256) void k4_agg1() {
    int node = (blockIdx.x * blockDim.x + threadIdx.x) >> 5;
    int lane = threadIdx.x & 31;
    if (node >= NN) return;
    const int beg = g_off[node], end = g_off[node + 1];
    const int srcg = lane & 0x1C;   // (h<<2): shfl source group base
    const int e4 = lane & 3;        // edge sub-index within head group
    const int e8 = lane & 7;        // edge index for src staging
    const int h = lane >> 2;
    const float edh = g_ed1[node * H1 + h];

    // prefetch batch 0 (pads zero-init -> s=0 row reads are safe)
    int   s_l = g_ssrc[beg + e8];
    int   sA  = __shfl_sync(FULLM, s_l, e4);
    int   sB  = __shfl_sync(FULLM, s_l, 4 + e4);
    float esA = g_es1[sA * H1 + h];
    float esB = g_es1[sB * H1 + h];

    float sumP = 0.f;
    unsigned long long acc0 = 0ull, acc1 = 0ull;
    for (int base = beg; base < end; base += 8) {
        // prefetch next batch's src + es gathers (overlaps with this batch's FMAs)
        int   s_n  = g_ssrc[base + 8 + e8];
        int   sAn  = __shfl_sync(FULLM, s_n, e4);
        int   sBn  = __shfl_sync(FULLM, s_n, 4 + e4);
        float esAn = g_es1[sAn * H1 + h];
        float esBn = g_es1[sBn * H1 + h];

        const int m = end - base;
        // lane (h, e4) owns p for edges e4 and 4+e4 of head h
        float pA = (e4 < m)     ? __expf(lrelu_f(esA + edh)) : 0.f;
        float pB = (4 + e4 < m) ? __expf(lrelu_f(esB + edh)) : 0.f;
        sumP += pA + pB;
#pragma unroll
        for (int j = 0; j < 8; j++) {
            int s   = __shfl_sync(FULLM, s_l, j);
            float p = __shfl_sync(FULLM, (j < 4) ? pA : pB, srcg | (j & 3));
            unsigned long long w2 = *(const unsigned long long*)
                &g_Wh1[s * O1 + 2 * lane];
            if (j & 1) fma2(acc1, pack2(p, p), w2);
            else       fma2(acc0, pack2(p, p), w2);
        }
        s_l = s_n; esA = esAn; esB = esBn;
    }
    // per-head sum: 4 lanes of group h jointly cover all edges
    sumP += __shfl_xor_sync(FULLM, sumP, 1);
    sumP += __shfl_xor_sync(FULLM, sumP, 2);

    const float inv = 1.f / (sumP + 1e-10f);
    float2 a0 = unpack2(acc0);
    float2 a1 = unpack2(acc1);
    *(float2*)&g_h1[node * O1 + 2 * lane] =
        make_float2(elu_f((a0.x + a1.x) * inv), elu_f((a0.y + a1.y) * inv));
}

// ========= K4c: GEMM2 (batched, W2 packed, f32x2) + es2/ed2 epilogue =========
#define G2_NB 64
__global__ __launch_bounds__(256) void k4c_gemm2(const float* __restrict__ a2s,
                                                 const float* __restrict__ a2d) {
    __shared__ float hs[G2_NB][O1];   // 16KB
    const int tid = threadIdx.x;
    const int lane = tid & 31;
    const int w = tid >> 5;
    const int nb0 = blockIdx.x * G2_NB;

    for (int idx = tid; idx < G2_NB * (O1 / 4); idx += 256) {
        int n = idx >> 4;
        int c = idx & 15;
        int g = nb0 + n;
        float4 v = make_float4(0.f, 0.f, 0.f, 0.f);
        if (g < NN) v = *(const float4*)&g_h1[(size_t)g * O1 + c * 4];
        *(float4*)&hs[n][c * 4] = v;
    }
    __syncthreads();

    unsigned long long acc[8][2];
#pragma unroll
    for (int n = 0; n < 8; n++) { acc[n][0] = 0ull; acc[n][1] = 0ull; }

    const int nrow = w * 8;
#pragma unroll 4
    for (int q = 0; q < O1 / 2; q += 2) {
        ulonglong2 wA = g_W2p[q * 32 + lane];
        ulonglong2 wB = g_W2p[(q + 1) * 32 + lane];
#pragma unroll
        for (int n = 0; n < 8; n++) {
            ulonglong2 xv = *(const ulonglong2*)&hs[nrow + n][2 * q];
            fma2(acc[n][0], xv.x, wA.x);
            fma2(acc[n][1], xv.x, wA.y);
            fma2(acc[n][0], xv.y, wB.x);
            fma2(acc[n][1], xv.y, wB.y);
        }
    }

    const float as0 = a2s[2 * lane], as1 = a2s[2 * lane + 1];
    const float ad0 = a2d[2 * lane], ad1 = a2d[2 * lane + 1];
#pragma unroll
    for (int n = 0; n < 8; n++) {
        int g = nb0 + w * 8 + n;
        if (g >= NN) continue;  // uniform across warp
        float2 p0 = unpack2(acc[n][0]);
        float2 p1 = unpack2(acc[n][1]);
        float o0 = p0.x + p0.y;
        float o1 = p1.x + p1.y;
        *(float2*)&g_Wh2[g * NLAB + 2 * lane] = make_float2(o0, o1);
        float ps = o0 * as0 + o1 * as1;
        float pd = o0 * ad0 + o1 * ad1;
#pragma unroll
        for (int o = 16; o; o >>= 1) {
            ps += __shfl_xor_sync(FULLM, ps, o);
            pd += __shfl_xor_sync(FULLM, pd, o);
        }
        if (lane == 0) { g_es2[g] = ps; g_ed2[g] = pd; }
    }
}

// ====== K5: layer-2 aggregate, batch-8 + sw-pipelined gather + softmax ======
__global__ __launch_bounds__(256) void k5_agg2(float* __restrict__ out) {
    int gid = blockIdx.x * blockDim.x + threadIdx.x;
    if (gid < NN) g_cnt[gid] = 0;   // leave cnt zeroed for the next call

    int node = gid >> 5;
    int lane = threadIdx.x & 31;
    if (node >= NN) return;
    const int beg = g_off[node], end = g_off[node + 1];
    const float ed = g_ed2[node];
    const int e8 = lane & 7;

    float sumP = 0.f;
    unsigned long long acc0 = 0ull, acc1 = 0ull;

    // depth-2 pipeline on the ssrc -> es2 gather chain (pads make loads safe)
    int   s_l = g_ssrc[beg + e8];
    float v_l = g_es2[s_l];
    for (int base = beg; base < end; base += 8) {
        int   s_n = g_ssrc[base + 8 + e8];
        float v_n = g_es2[s_n];

        const int m = end - base;
        float p_l = (e8 < m) ? __expf(lrelu_f(v_l + ed)) : 0.f;
        if (lane < 8) sumP += p_l;   // lanes 8-31 hold duplicates
#pragma unroll
        for (int j = 0; j < 8; j++) {
            int s   = __shfl_sync(FULLM, s_l, j);
            float p = __shfl_sync(FULLM, p_l, j);
            unsigned long long w2 = *(const unsigned long long*)
                &g_Wh2[s * NLAB + 2 * lane];
            if (j & 1) fma2(acc1, pack2(p, p), w2);
            else       fma2(acc0, pack2(p, p), w2);
        }
        s_l = s_n; v_l = v_n;
    }
#pragma unroll
    for (int o = 16; o; o >>= 1) sumP += __shfl_xor_sync(FULLM, sumP, o);

    const float inv = 1.f / (sumP + 1e-10f);
    float2 a0 = unpack2(acc0);
    float2 a1 = unpack2(acc1);
    float o0 = (a0.x + a1.x) * inv;
    float o1 = (a0.y + a1.y) * inv;

    // head-mean is identity (H2=1); fused softmax over 64 classes
    float m2 = fmaxf(o0, o1);
#pragma unroll
    for (int o = 16; o; o >>= 1) m2 = fmaxf(m2, __shfl_xor_sync(FULLM, m2, o));
    float e0 = __expf(o0 - m2);
    float e1 = __expf(o1 - m2);
    float s2 = e0 + e1;
#pragma unroll
    for (int o = 16; o; o >>= 1) s2 += __shfl_xor_sync(FULLM, s2, o);
    float r = 1.f / s2;
    *(float2*)&out[(size_t)node * NLAB + 2 * lane] = make_float2(e0 * r, e1 * r);
}

// ---------------- launch ----------------
extern "C" void kernel_launch(void* const* d_in, const int* in_sizes, int n_in,
                              void* d_out, int out_size) {
    const float* x    = (const float*)d_in[0];
    const float* W1   = (const float*)d_in[1];
    const float* a1s  = (const float*)d_in[2];
    const float* a1d  = (const float*)d_in[3];
    const float* W2   = (const float*)d_in[4];
    const float* a2s  = (const float*)d_in[5];
    const float* a2d  = (const float*)d_in[6];
    const int*   src  = (const int*)d_in[7];
    const int*   dst  = (const int*)d_in[8];
    float* out = (float*)d_out;

    k1_prep_hist<<<36 + HIST4_BLKS, 256>>>(W1, W2, dst);
    k2_gemm1_scan<<<1 + (NN + G1_NB - 1) / G1_NB, 256>>>(x, a1s, a1d);
    k3_scatter<<<HIST4_BLKS, 256>>>(src, dst);
    k4_agg1<<<(NN * 32 + 255) / 256, 256>>>();
    k4c_gemm2<<<(NN + G2_NB - 1) / G2_NB, 256>>>(a2s, a2d);
    k5_agg2<<<(NN * 32 + 255) / 256, 256>>>(out);
}

// round 12
// speedup vs baseline: 1.1865x; 1.0679x over previous
#include <cuda_runtime.h>
#include <cuda_bf16.h>
#include <math.h>

// ---------------- problem constants ----------------
#define NN 50000
#define EE 800000
#define F_IN 512
#define H1 8
#define F_HID 8
#define O1 64          // H1*F_HID
#define NLAB 64
#define LRELU 0.2f

#define FULLM 0xffffffffu

// ---------------- device scratch (no allocs allowed) ----------------
__device__ ulonglong2 g_Wp[(F_IN / 2) * 32];   // W1 packed: [kpair][lane] -> {(o=2l),(o=2l+1)} f32x2
__device__ ulonglong2 g_W2p[(O1 / 2) * 32];    // W2 packed same format
__device__ float g_Wh1[(size_t)NN * O1];       // layer-1 node features
__device__ float g_es1[NN * H1];
__device__ float g_ed1[NN * H1];
__device__ float g_h1[(size_t)NN * O1];        // post-aggregation, post-ELU
__device__ float g_Wh2[(size_t)NN * NLAB];
__device__ float g_es2[NN];
__device__ float g_ed2[NN];
__device__ int   g_cnt[NN];                    // zero at entry (re-zeroed at tail of k5)
__device__ int   g_rank[EE];
__device__ int   g_off[NN + 1];
__device__ int   g_ssrc[EE + 64];              // +pad (zero-init) for unguarded pipelined loads

// ---------------- f32x2 helpers (dense GEMMs only) ----------------
__device__ __forceinline__ unsigned long long pack2(float lo, float hi) {
    unsigned long long r;
    asm("mov.b64 %0, {%1, %2};" : "=l"(r) : "f"(lo), "f"(hi));
    return r;
}
__device__ __forceinline__ void fma2(unsigned long long& acc, unsigned long long a,
                                     unsigned long long b) {
    asm("fma.rn.f32x2 %0, %1, %2, %0;" : "+l"(acc) : "l"(a), "l"(b));
}
__device__ __forceinline__ float2 unpack2(unsigned long long v) {
    float lo, hi;
    asm("mov.b64 {%0, %1}, %2;" : "=f"(lo), "=f"(hi) : "l"(v));
    return make_float2(lo, hi);
}

__device__ __forceinline__ float lrelu_f(float v) { return fmaxf(v, LRELU * v); }
__device__ __forceinline__ float elu_f(float v)   { return v > 0.f ? v : __expf(v) - 1.f; }

// ================= KP: pack W1 (32 blk) + pack W2 (4 blk)  [chain B] =================
__global__ __launch_bounds__(256) void kpack(const float* __restrict__ W1,
                                             const float* __restrict__ W2) {
    const int bid = blockIdx.x;
    const int tid = threadIdx.x;
    if (bid < 32) {
        int i = bid * 256 + tid;   // < 8192 = (F_IN/2)*32
        int p = i >> 5, l = i & 31;
        int o0 = 2 * l, o1 = 2 * l + 1;
        int k0 = 2 * p, k1 = 2 * p + 1;
        // W1: [H1, F_IN, F_HID]; element (k,o) at (o>>3)*4096 + k*8 + (o&7)
        float w00 = W1[(o0 >> 3) * (F_IN * F_HID) + k0 * F_HID + (o0 & 7)];
        float w10 = W1[(o0 >> 3) * (F_IN * F_HID) + k1 * F_HID + (o0 & 7)];
        float w01 = W1[(o1 >> 3) * (F_IN * F_HID) + k0 * F_HID + (o1 & 7)];
        float w11 = W1[(o1 >> 3) * (F_IN * F_HID) + k1 * F_HID + (o1 & 7)];
        ulonglong2 v;
        v.x = pack2(w00, w10);
        v.y = pack2(w01, w11);
        g_Wp[i] = v;
    } else {
        int i = (bid - 32) * 256 + tid;   // < 1024 = (O1/2)*32
        int p = i >> 5, l = i & 31;
        int o0 = 2 * l, o1 = 2 * l + 1;
        int k0 = 2 * p, k1 = 2 * p + 1;
        // W2: [1, O1, NLAB]; element (k,o) at k*64 + o
        ulonglong2 v;
        v.x = pack2(W2[k0 * NLAB + o0], W2[k1 * NLAB + o0]);
        v.y = pack2(W2[k0 * NLAB + o1], W2[k1 * NLAB + o1]);
        g_W2p[i] = v;
    }
}

// ================= KH: hist ×4 vectorized (rank-storing)  [chain A] =================
#define HIST4_BLKS ((EE + 1023) / 1024)
__global__ __launch_bounds__(256) void khist(const int* __restrict__ dst) {
    int e = (blockIdx.x * blockDim.x + threadIdx.x) * 4;
    if (e + 3 < EE) {
        int4 d4 = *(const int4*)&dst[e];
        int4 r4;
        r4.x = atomicAdd(&g_cnt[d4.x], 1);
        r4.y = atomicAdd(&g_cnt[d4.y], 1);
        r4.z = atomicAdd(&g_cnt[d4.z], 1);
        r4.w = atomicAdd(&g_cnt[d4.w], 1);
        *(int4*)&g_rank[e] = r4;
    } else {
        for (int q = e; q < EE; q++) g_rank[q] = atomicAdd(&g_cnt[dst[q]], 1);
    }
}

// ================= KS: exclusive scan g_cnt -> g_off  [chain A] =================
__global__ __launch_bounds__(256) void kscan() {
    __shared__ int ssum[256];
    const int tid = threadIdx.x;
    const int CH = (NN + 255) / 256;   // 196
    int b = tid * CH;
    int e2 = b + CH; if (e2 > NN) e2 = NN;
    int s = 0;
    for (int i = b; i < e2; i++) s += g_cnt[i];
    ssum[tid] = s;
    __syncthreads();
    for (int d = 1; d < 256; d <<= 1) {
        int v = (tid >= d) ? ssum[tid - d] : 0;
        __syncthreads();
        ssum[tid] += v;
        __syncthreads();
    }
    int off = (tid == 0) ? 0 : ssum[tid - 1];
    for (int i = b; i < e2; i++) {
        g_off[i] = off;
        off += g_cnt[i];
    }
    if (tid == 255) g_off[NN] = ssum[255];
}

// ================= K2: gemm1 (pure) + es1/ed1 epilogue  [chain B] =================
#define G1_NB 64
#define G1_KC 128
__global__ __launch_bounds__(256) void k2_gemm1(const float* __restrict__ x,
                                                const float* __restrict__ a1s,
                                                const float* __restrict__ a1d) {
    __shared__ float xs[G1_NB][G1_KC];   // 32KB
    const int tid = threadIdx.x;
    const int lane = tid & 31;
    const int w = tid >> 5;
    const int nb0 = blockIdx.x * G1_NB;

    unsigned long long acc[8][2];
#pragma unroll
    for (int n = 0; n < 8; n++) { acc[n][0] = 0ull; acc[n][1] = 0ull; }

    for (int kt = 0; kt < F_IN; kt += G1_KC) {
        __syncthreads();
        for (int idx = tid; idx < G1_NB * (G1_KC / 4); idx += 256) {
            int n = idx >> 5;
            int c = idx & 31;
            int g = nb0 + n;
            float4 v = make_float4(0.f, 0.f, 0.f, 0.f);
            if (g < NN) v = *(const float4*)&x[(size_t)g * F_IN + kt + c * 4];
            *(float4*)&xs[n][c * 4] = v;
        }
        __syncthreads();

        const int nrow = w * 8;
        const int pbase = kt >> 1;
#pragma unroll 4
        for (int q = 0; q < G1_KC / 2; q += 2) {
            ulonglong2 wA = g_Wp[(pbase + q) * 32 + lane];
            ulonglong2 wB = g_Wp[(pbase + q + 1) * 32 + lane];
#pragma unroll
            for (int n = 0; n < 8; n++) {
                ulonglong2 xv = *(const ulonglong2*)&xs[nrow + n][2 * q];
                fma2(acc[n][0], xv.x, wA.x);
                fma2(acc[n][1], xv.x, wA.y);
                fma2(acc[n][0], xv.y, wB.x);
                fma2(acc[n][1], xv.y, wB.y);
            }
        }
    }

    const float as0 = a1s[2 * lane], as1 = a1s[2 * lane + 1];
    const float ad0 = a1d[2 * lane], ad1 = a1d[2 * lane + 1];
#pragma unroll
    for (int n = 0; n < 8; n++) {
        int g = nb0 + w * 8 + n;
        if (g >= NN) continue;  // uniform across warp
        float2 p0 = unpack2(acc[n][0]);
        float2 p1 = unpack2(acc[n][1]);
        float o0 = p0.x + p0.y;
        float o1 = p1.x + p1.y;
        *(float2*)&g_Wh1[g * O1 + 2 * lane] = make_float2(o0, o1);
        float ps = o0 * as0 + o1 * as1;
        float pd = o0 * ad0 + o1 * ad1;
        ps += __shfl_xor_sync(FULLM, ps, 1);
        ps += __shfl_xor_sync(FULLM, ps, 2);
        pd += __shfl_xor_sync(FULLM, pd, 1);
        pd += __shfl_xor_sync(FULLM, pd, 2);
        if ((lane & 3) == 0) {
            g_es1[g * H1 + (lane >> 2)] = ps;
            g_ed1[g * H1 + (lane >> 2)] = pd;
        }
    }
}

// ============ K3: pure scatter (atomic-free, rank-based), ×4  [chain A] ============
__global__ void k3_scatter(const int* __restrict__ src, const int* __restrict__ dst) {
    int e = (blockIdx.x * blockDim.x + threadIdx.x) * 4;
    if (e + 3 < EE) {
        int4 d4 = *(const int4*)&dst[e];
        int4 s4 = *(const int4*)&src[e];
        int4 r4 = *(const int4*)&g_rank[e];
        g_ssrc[g_off[d4.x] + r4.x] = s4.x;
        g_ssrc[g_off[d4.y] + r4.y] = s4.y;
        g_ssrc[g_off[d4.z] + r4.z] = s4.z;
        g_ssrc[g_off[d4.w] + r4.w] = s4.w;
    } else {
        for (int q = e; q < EE; q++) g_ssrc[g_off[dst[q]] + g_rank[q]] = src[q];
    }
}

// ====== K4: layer-1 aggregate, batch-8, inline p (pipelined es1 gather) + ELU ======
__global__ __launch_bounds__(256) void k4_agg1() {
    int node = (blockIdx.x * blockDim.x + threadIdx.x) >> 5;
    int lane = threadIdx.x & 31;
    if (node >= NN) return;
    const int beg = g_off[node], end = g_off[node + 1];
    const int srcg = lane & 0x1C;   // (h<<2): shfl source group base
    const int e4 = lane & 3;        // edge sub-index within head group
    const int e8 = lane & 7;        // edge index for src staging
    const int h = lane >> 2;
    const float edh = g_ed1[node * H1 + h];

    // prefetch batch 0 (pads zero-init -> s=0 row reads are safe)
    int   s_l = g_ssrc[beg + e8];
    int   sA  = __shfl_sync(FULLM, s_l, e4);
    int   sB  = __shfl_sync(FULLM, s_l, 4 + e4);
    float esA = g_es1[sA * H1 + h];
    float esB = g_es1[sB * H1 + h];

    float sumP = 0.f;
    unsigned long long acc0 = 0ull, acc1 = 0ull;
    for (int base = beg; base < end; base += 8) {
        // prefetch next batch's src + es gathers (overlaps with this batch's FMAs)
        int   s_n  = g_ssrc[base + 8 + e8];
        int   sAn  = __shfl_sync(FULLM, s_n, e4);
        int   sBn  = __shfl_sync(FULLM, s_n, 4 + e4);
        float esAn = g_es1[sAn * H1 + h];
        float esBn = g_es1[sBn * H1 + h];

        const int m = end - base;
        // lane (h, e4) owns p for edges e4 and 4+e4 of head h
        float pA = (e4 < m)     ? __expf(lrelu_f(esA + edh)) : 0.f;
        float pB = (4 + e4 < m) ? __expf(lrelu_f(esB + edh)) : 0.f;
        sumP += pA + pB;
#pragma unroll
        for (int j = 0; j < 8; j++) {
            int s   = __shfl_sync(FULLM, s_l, j);
            float p = __shfl_sync(FULLM, (j < 4) ? pA : pB, srcg | (j & 3));
            unsigned long long w2 = *(const unsigned long long*)
                &g_Wh1[s * O1 + 2 * lane];
            if (j & 1) fma2(acc1, pack2(p, p), w2);
            else       fma2(acc0, pack2(p, p), w2);
        }
        s_l = s_n; esA = esAn; esB = esBn;
    }
    // per-head sum: 4 lanes of group h jointly cover all edges
    sumP += __shfl_xor_sync(FULLM, sumP, 1);
    sumP += __shfl_xor_sync(FULLM, sumP, 2);

    const float inv = 1.f / (sumP + 1e-10f);
    float2 a0 = unpack2(acc0);
    float2 a1 = unpack2(acc1);
    *(float2*)&g_h1[node * O1 + 2 * lane] =
        make_float2(elu_f((a0.x + a1.x) * inv), elu_f((a0.y + a1.y) * inv));
}

// ========= K4c: GEMM2 (batched, W2 packed, f32x2) + es2/ed2 epilogue =========
#define G2_NB 64
__global__ __launch_bounds__(256) void k4c_gemm2(const float* __restrict__ a2s,
                                                 const float* __restrict__ a2d) {
    __shared__ float hs[G2_NB][O1];   // 16KB
    const int tid = threadIdx.x;
    const int lane = tid & 31;
    const int w = tid >> 5;
    const int nb0 = blockIdx.x * G2_NB;

    for (int idx = tid; idx < G2_NB * (O1 / 4); idx += 256) {
        int n = idx >> 4;
        int c = idx & 15;
        int g = nb0 + n;
        float4 v = make_float4(0.f, 0.f, 0.f, 0.f);
        if (g < NN) v = *(const float4*)&g_h1[(size_t)g * O1 + c * 4];
        *(float4*)&hs[n][c * 4] = v;
    }
    __syncthreads();

    unsigned long long acc[8][2];
#pragma unroll
    for (int n = 0; n < 8; n++) { acc[n][0] = 0ull; acc[n][1] = 0ull; }

    const int nrow = w * 8;
#pragma unroll 4
    for (int q = 0; q < O1 / 2; q += 2) {
        ulonglong2 wA = g_W2p[q * 32 + lane];
        ulonglong2 wB = g_W2p[(q + 1) * 32 + lane];
#pragma unroll
        for (int n = 0; n < 8; n++) {
            ulonglong2 xv = *(const ulonglong2*)&hs[nrow + n][2 * q];
            fma2(acc[n][0], xv.x, wA.x);
            fma2(acc[n][1], xv.x, wA.y);
            fma2(acc[n][0], xv.y, wB.x);
            fma2(acc[n][1], xv.y, wB.y);
        }
    }

    const float as0 = a2s[2 * lane], as1 = a2s[2 * lane + 1];
    const float ad0 = a2d[2 * lane], ad1 = a2d[2 * lane + 1];
#pragma unroll
    for (int n = 0; n < 8; n++) {
        int g = nb0 + w * 8 + n;
        if (g >= NN) continue;  // uniform across warp
        float2 p0 = unpack2(acc[n][0]);
        float2 p1 = unpack2(acc[n][1]);
        float o0 = p0.x + p0.y;
        float o1 = p1.x + p1.y;
        *(float2*)&g_Wh2[g * NLAB + 2 * lane] = make_float2(o0, o1);
        float ps = o0 * as0 + o1 * as1;
        float pd = o0 * ad0 + o1 * ad1;
#pragma unroll
        for (int o = 16; o; o >>= 1) {
            ps += __shfl_xor_sync(FULLM, ps, o);
            pd += __shfl_xor_sync(FULLM, pd, o);
        }
        if (lane == 0) { g_es2[g] = ps; g_ed2[g] = pd; }
    }
}

// ====== K5: layer-2 aggregate, batch-8 + sw-pipelined gather + softmax ======
__global__ __launch_bounds__(256) void k5_agg2(float* __restrict__ out) {
    int gid = blockIdx.x * blockDim.x + threadIdx.x;
    if (gid < NN) g_cnt[gid] = 0;   // leave cnt zeroed for the next call

    int node = gid >> 5;
    int lane = threadIdx.x & 31;
    if (node >= NN) return;
    const int beg = g_off[node], end = g_off[node + 1];
    const float ed = g_ed2[node];
    const int e8 = lane & 7;

    float sumP = 0.f;
    unsigned long long acc0 = 0ull, acc1 = 0ull;

    // depth-2 pipeline on the ssrc -> es2 gather chain (pads make loads safe)
    int   s_l = g_ssrc[beg + e8];
    float v_l = g_es2[s_l];
    for (int base = beg; base < end; base += 8) {
        int   s_n = g_ssrc[base + 8 + e8];
        float v_n = g_es2[s_n];

        const int m = end - base;
        float p_l = (e8 < m) ? __expf(lrelu_f(v_l + ed)) : 0.f;
        if (lane < 8) sumP += p_l;   // lanes 8-31 hold duplicates
#pragma unroll
        for (int j = 0; j < 8; j++) {
            int s   = __shfl_sync(FULLM, s_l, j);
            float p = __shfl_sync(FULLM, p_l, j);
            unsigned long long w2 = *(const unsigned long long*)
                &g_Wh2[s * NLAB + 2 * lane];
            if (j & 1) fma2(acc1, pack2(p, p), w2);
            else       fma2(acc0, pack2(p, p), w2);
        }
        s_l = s_n; v_l = v_n;
    }
#pragma unroll
    for (int o = 16; o; o >>= 1) sumP += __shfl_xor_sync(FULLM, sumP, o);

    const float inv = 1.f / (sumP + 1e-10f);
    float2 a0 = unpack2(acc0);
    float2 a1 = unpack2(acc1);
    float o0 = (a0.x + a1.x) * inv;
    float o1 = (a0.y + a1.y) * inv;

    // head-mean is identity (H2=1); fused softmax over 64 classes
    float m2 = fmaxf(o0, o1);
#pragma unroll
    for (int o = 16; o; o >>= 1) m2 = fmaxf(m2, __shfl_xor_sync(FULLM, m2, o));
    float e0 = __expf(o0 - m2);
    float e1 = __expf(o1 - m2);
    float s2 = e0 + e1;
#pragma unroll
    for (int o = 16; o; o >>= 1) s2 += __shfl_xor_sync(FULLM, s2, o);
    float r = 1.f / s2;
    *(float2*)&out[(size_t)node * NLAB + 2 * lane] = make_float2(e0 * r, e1 * r);
}

// ---------------- launch: fork/join — chain A (edge prep) ∥ chain B (dense) ----------------
extern "C" void kernel_launch(void* const* d_in, const int* in_sizes, int n_in,
                              void* d_out, int out_size) {
    const float* x    = (const float*)d_in[0];
    const float* W1   = (const float*)d_in[1];
    const float* a1s  = (const float*)d_in[2];
    const float* a1d  = (const float*)d_in[3];
    const float* W2   = (const float*)d_in[4];
    const float* a2s  = (const float*)d_in[5];
    const float* a2d  = (const float*)d_in[6];
    const int*   src  = (const int*)d_in[7];
    const int*   dst  = (const int*)d_in[8];
    float* out = (float*)d_out;

    // one-time host-side resources (no device memory; identical work every call)
    static cudaStream_t sB = nullptr;
    static cudaEvent_t evFork = nullptr, evJoin = nullptr;
    if (sB == nullptr) {
        cudaStreamCreateWithFlags(&sB, cudaStreamNonBlocking);
        cudaEventCreateWithFlags(&evFork, cudaEventDisableTiming);
        cudaEventCreateWithFlags(&evJoin, cudaEventDisableTiming);
    }

    // fork: bring side stream into the same dependency chain / capture graph
    cudaEventRecord(evFork, 0);
    cudaStreamWaitEvent(sB, evFork, 0);

    // chain B (side stream): weight pack -> gemm1 (+es1/ed1)
    kpack<<<36, 256, 0, sB>>>(W1, W2);
    k2_gemm1<<<(NN + G1_NB - 1) / G1_NB, 256, 0, sB>>>(x, a1s, a1d);

    // chain A (main stream): hist -> scan -> scatter
    khist<<<HIST4_BLKS, 256>>>(dst);
    kscan<<<1, 256>>>();
    k3_scatter<<<HIST4_BLKS, 256>>>(src, dst);

    // join
    cudaEventRecord(evJoin, sB);
    cudaStreamWaitEvent(0, evJoin, 0);

    // serial tail
    k4_agg1<<<(NN * 32 + 255) / 256, 256>>>();
    k4c_gemm2<<<(NN + G2_NB - 1) / G2_NB, 256>>>(a2s, a2d);
    k5_agg2<<<(NN * 32 + 255) / 256, 256>>>(out);
}

// round 13
// speedup vs baseline: 1.2305x; 1.0371x over previous
#include <cuda_runtime.h>
#include <cuda_bf16.h>
#include <math.h>

// ---------------- problem constants ----------------
#define NN 50000
#define EE 800000
#define F_IN 512
#define H1 8
#define F_HID 8
#define O1 64          // H1*F_HID
#define NLAB 64
#define LRELU 0.2f

#define FULLM 0xffffffffu
#define SCAN_BLKS ((NN + 255) / 256)   // 196

// ---------------- device scratch (no allocs allowed) ----------------
__device__ ulonglong2 g_Wp[(F_IN / 2) * 32];   // W1 packed: [kpair][lane] -> {(o=2l),(o=2l+1)} f32x2
__device__ ulonglong2 g_W2p[(O1 / 2) * 32];    // W2 packed same format
__device__ float g_Wh1[(size_t)NN * O1];       // layer-1 node features
__device__ float g_es1[NN * H1];
__device__ float g_ed1[NN * H1];
__device__ float g_h1[(size_t)NN * O1];        // post-aggregation, post-ELU
__device__ float g_Wh2[(size_t)NN * NLAB];
__device__ float g_es2[NN];
__device__ float g_ed2[NN];
__device__ int   g_cnt[NN];                    // zero at entry (re-zeroed at tail of k5)
__device__ int   g_rank[EE];
__device__ int   g_off[NN + 1];
__device__ int   g_bsum[256];                  // per-block totals (scan phase A)
__device__ int   g_bscan[256];                 // scanned block offsets (phase B)
__device__ int   g_ssrc[EE + 64];              // +pad (zero-init) for unguarded pipelined loads

// ---------------- f32x2 helpers (dense GEMMs only) ----------------
__device__ __forceinline__ unsigned long long pack2(float lo, float hi) {
    unsigned long long r;
    asm("mov.b64 %0, {%1, %2};" : "=l"(r) : "f"(lo), "f"(hi));
    return r;
}
__device__ __forceinline__ void fma2(unsigned long long& acc, unsigned long long a,
                                     unsigned long long b) {
    asm("fma.rn.f32x2 %0, %1, %2, %0;" : "+l"(acc) : "l"(a), "l"(b));
}
__device__ __forceinline__ float2 unpack2(unsigned long long v) {
    float lo, hi;
    asm("mov.b64 {%0, %1}, %2;" : "=f"(lo), "=f"(hi) : "l"(v));
    return make_float2(lo, hi);
}

__device__ __forceinline__ float lrelu_f(float v) { return fmaxf(v, LRELU * v); }
__device__ __forceinline__ float elu_f(float v)   { return v > 0.f ? v : __expf(v) - 1.f; }

// ================= KP: pack W1 (32 blk) + pack W2 (4 blk)  [chain B] =================
__global__ __launch_bounds__(256) void kpack(const float* __restrict__ W1,
                                             const float* __restrict__ W2) {
    const int bid = blockIdx.x;
    const int tid = threadIdx.x;
    if (bid < 32) {
        int i = bid * 256 + tid;   // < 8192 = (F_IN/2)*32
        int p = i >> 5, l = i & 31;
        int o0 = 2 * l, o1 = 2 * l + 1;
        int k0 = 2 * p, k1 = 2 * p + 1;
        // W1: [H1, F_IN, F_HID]; element (k,o) at (o>>3)*4096 + k*8 + (o&7)
        float w00 = W1[(o0 >> 3) * (F_IN * F_HID) + k0 * F_HID + (o0 & 7)];
        float w10 = W1[(o0 >> 3) * (F_IN * F_HID) + k1 * F_HID + (o0 & 7)];
        float w01 = W1[(o1 >> 3) * (F_IN * F_HID) + k0 * F_HID + (o1 & 7)];
        float w11 = W1[(o1 >> 3) * (F_IN * F_HID) + k1 * F_HID + (o1 & 7)];
        ulonglong2 v;
        v.x = pack2(w00, w10);
        v.y = pack2(w01, w11);
        g_Wp[i] = v;
    } else {
        int i = (bid - 32) * 256 + tid;   // < 1024 = (O1/2)*32
        int p = i >> 5, l = i & 31;
        int o0 = 2 * l, o1 = 2 * l + 1;
        int k0 = 2 * p, k1 = 2 * p + 1;
        // W2: [1, O1, NLAB]; element (k,o) at k*64 + o
        ulonglong2 v;
        v.x = pack2(W2[k0 * NLAB + o0], W2[k1 * NLAB + o0]);
        v.y = pack2(W2[k0 * NLAB + o1], W2[k1 * NLAB + o1]);
        g_W2p[i] = v;
    }
}

// ================= KH: hist ×4 vectorized (rank-storing)  [chain A] =================
#define HIST4_BLKS ((EE + 1023) / 1024)
__global__ __launch_bounds__(256) void khist(const int* __restrict__ dst) {
    int e = (blockIdx.x * blockDim.x + threadIdx.x) * 4;
    if (e + 3 < EE) {
        int4 d4 = *(const int4*)&dst[e];
        int4 r4;
        r4.x = atomicAdd(&g_cnt[d4.x], 1);
        r4.y = atomicAdd(&g_cnt[d4.y], 1);
        r4.z = atomicAdd(&g_cnt[d4.z], 1);
        r4.w = atomicAdd(&g_cnt[d4.w], 1);
        *(int4*)&g_rank[e] = r4;
    } else {
        for (int q = e; q < EE; q++) g_rank[q] = atomicAdd(&g_cnt[dst[q]], 1);
    }
}

// ---- block-local inclusive scan helper (256 threads) -> returns inclusive value;
//      *total gets the block sum
__device__ __forceinline__ int block_scan_incl_256(int v, int tid, int* wsum) {
    const int lane = tid & 31, wid = tid >> 5;
    int x = v;
#pragma unroll
    for (int d = 1; d < 32; d <<= 1) {
        int y = __shfl_up_sync(FULLM, x, d);
        if (lane >= d) x += y;
    }
    if (lane == 31) wsum[wid] = x;
    __syncthreads();
    if (wid == 0) {
        int s = (lane < 8) ? wsum[lane] : 0;
#pragma unroll
        for (int d = 1; d < 8; d <<= 1) {
            int y = __shfl_up_sync(FULLM, s, d);
            if (lane >= d) s += y;
        }
        if (lane < 8) wsum[lane] = s;
    }
    __syncthreads();
    return x + (wid ? wsum[wid - 1] : 0);
}

// ================= KSa: block-local exclusive scan of g_cnt  [chain A] =================
__global__ __launch_bounds__(256) void kscan_a() {
    __shared__ int wsum[8];
    const int b = blockIdx.x, t = threadIdx.x;
    const int i = b * 256 + t;
    int v = (i < NN) ? g_cnt[i] : 0;
    int incl = block_scan_incl_256(v, t, wsum);
    if (i < NN) g_off[i] = incl - v;          // local exclusive
    if (t == 255) g_bsum[b] = incl;           // block total
}

// ================= KSb: scan of block totals (1 block)  [chain A] =================
__global__ __launch_bounds__(256) void kscan_b() {
    __shared__ int wsum[8];
    const int t = threadIdx.x;
    int v = (t < SCAN_BLKS) ? g_bsum[t] : 0;
    int incl = block_scan_incl_256(v, t, wsum);
    g_bscan[t] = incl - v;                    // exclusive block offset
    if (t == 255) g_off[NN] = incl;           // grand total = EE
}

// ================= KSc: apply block offsets  [chain A] =================
__global__ __launch_bounds__(256) void kscan_c() {
    const int b = blockIdx.x, t = threadIdx.x;
    const int i = b * 256 + t;
    if (i < NN) g_off[i] += g_bscan[b];
}

// ================= K2: gemm1 (pure) + es1/ed1 epilogue  [chain B] =================
#define G1_NB 64
#define G1_KC 128
__global__ __launch_bounds__(256) void k2_gemm1(const float* __restrict__ x,
                                                const float* __restrict__ a1s,
                                                const float* __restrict__ a1d) {
    __shared__ float xs[G1_NB][G1_KC];   // 32KB
    const int tid = threadIdx.x;
    const int lane = tid & 31;
    const int w = tid >> 5;
    const int nb0 = blockIdx.x * G1_NB;

    unsigned long long acc[8][2];
#pragma unroll
    for (int n = 0; n < 8; n++) { acc[n][0] = 0ull; acc[n][1] = 0ull; }

    for (int kt = 0; kt < F_IN; kt += G1_KC) {
        __syncthreads();
        for (int idx = tid; idx < G1_NB * (G1_KC / 4); idx += 256) {
            int n = idx >> 5;
            int c = idx & 31;
            int g = nb0 + n;
            float4 v = make_float4(0.f, 0.f, 0.f, 0.f);
            if (g < NN) v = *(const float4*)&x[(size_t)g * F_IN + kt + c * 4];
            *(float4*)&xs[n][c * 4] = v;
        }
        __syncthreads();

        const int nrow = w * 8;
        const int pbase = kt >> 1;
#pragma unroll 4
        for (int q = 0; q < G1_KC / 2; q += 2) {
            ulonglong2 wA = g_Wp[(pbase + q) * 32 + lane];
            ulonglong2 wB = g_Wp[(pbase + q + 1) * 32 + lane];
#pragma unroll
            for (int n = 0; n < 8; n++) {
                ulonglong2 xv = *(const ulonglong2*)&xs[nrow + n][2 * q];
                fma2(acc[n][0], xv.x, wA.x);
                fma2(acc[n][1], xv.x, wA.y);
                fma2(acc[n][0], xv.y, wB.x);
                fma2(acc[n][1], xv.y, wB.y);
            }
        }
    }

    const float as0 = a1s[2 * lane], as1 = a1s[2 * lane + 1];
    const float ad0 = a1d[2 * lane], ad1 = a1d[2 * lane + 1];
#pragma unroll
    for (int n = 0; n < 8; n++) {
        int g = nb0 + w * 8 + n;
        if (g >= NN) continue;  // uniform across warp
        float2 p0 = unpack2(acc[n][0]);
        float2 p1 = unpack2(acc[n][1]);
        float o0 = p0.x + p0.y;
        float o1 = p1.x + p1.y;
        *(float2*)&g_Wh1[g * O1 + 2 * lane] = make_float2(o0, o1);
        float ps = o0 * as0 + o1 * as1;
        float pd = o0 * ad0 + o1 * ad1;
        ps += __shfl_xor_sync(FULLM, ps, 1);
        ps += __shfl_xor_sync(FULLM, ps, 2);
        pd += __shfl_xor_sync(FULLM, pd, 1);
        pd += __shfl_xor_sync(FULLM, pd, 2);
        if ((lane & 3) == 0) {
            g_es1[g * H1 + (lane >> 2)] = ps;
            g_ed1[g * H1 + (lane >> 2)] = pd;
        }
    }
}

// ============ K3: pure scatter (atomic-free, rank-based), ×4  [chain A] ============
__global__ void k3_scatter(const int* __restrict__ src, const int* __restrict__ dst) {
    int e = (blockIdx.x * blockDim.x + threadIdx.x) * 4;
    if (e + 3 < EE) {
        int4 d4 = *(const int4*)&dst[e];
        int4 s4 = *(const int4*)&src[e];
        int4 r4 = *(const int4*)&g_rank[e];
        g_ssrc[g_off[d4.x] + r4.x] = s4.x;
        g_ssrc[g_off[d4.y] + r4.y] = s4.y;
        g_ssrc[g_off[d4.z] + r4.z] = s4.z;
        g_ssrc[g_off[d4.w] + r4.w] = s4.w;
    } else {
        for (int q = e; q < EE; q++) g_ssrc[g_off[dst[q]] + g_rank[q]] = src[q];
    }
}

// ====== K4: layer-1 aggregate, batch-8, inline p (pipelined es1 gather) + ELU ======
__global__ __launch_bounds__(256) void k4_agg1() {
    int node = (blockIdx.x * blockDim.x + threadIdx.x) >> 5;
    int lane = threadIdx.x & 31;
    if (node >= NN) return;
    const int beg = g_off[node], end = g_off[node + 1];
    const int srcg = lane & 0x1C;   // (h<<2): shfl source group base
    const int e4 = lane & 3;        // edge sub-index within head group
    const int e8 = lane & 7;        // edge index for src staging
    const int h = lane >> 2;
    const float edh = g_ed1[node * H1 + h];

    // prefetch batch 0 (pads zero-init -> s=0 row reads are safe)
    int   s_l = g_ssrc[beg + e8];
    int   sA  = __shfl_sync(FULLM, s_l, e4);
    int   sB  = __shfl_sync(FULLM, s_l, 4 + e4);
    float esA = g_es1[sA * H1 + h];
    float esB = g_es1[sB * H1 + h];

    float sumP = 0.f;
    unsigned long long acc0 = 0ull, acc1 = 0ull;
    for (int base = beg; base < end; base += 8) {
        // prefetch next batch's src + es gathers (overlaps with this batch's FMAs)
        int   s_n  = g_ssrc[base + 8 + e8];
        int   sAn  = __shfl_sync(FULLM, s_n, e4);
        int   sBn  = __shfl_sync(FULLM, s_n, 4 + e4);
        float esAn = g_es1[sAn * H1 + h];
        float esBn = g_es1[sBn * H1 + h];

        const int m = end - base;
        // lane (h, e4) owns p for edges e4 and 4+e4 of head h
        float pA = (e4 < m)     ? __expf(lrelu_f(esA + edh)) : 0.f;
        float pB = (4 + e4 < m) ? __expf(lrelu_f(esB + edh)) : 0.f;
        sumP += pA + pB;
#pragma unroll
        for (int j = 0; j < 8; j++) {
            int s   = __shfl_sync(FULLM, s_l, j);
            float p = __shfl_sync(FULLM, (j < 4) ? pA : pB, srcg | (j & 3));
            unsigned long long w2 = *(const unsigned long long*)
                &g_Wh1[s * O1 + 2 * lane];
            if (j & 1) fma2(acc1, pack2(p, p), w2);
            else       fma2(acc0, pack2(p, p), w2);
        }
        s_l = s_n; esA = esAn; esB = esBn;
    }
    // per-head sum: 4 lanes of group h jointly cover all edges
    sumP += __shfl_xor_sync(FULLM, sumP, 1);
    sumP += __shfl_xor_sync(FULLM, sumP, 2);

    const float inv = 1.f / (sumP + 1e-10f);
    float2 a0 = unpack2(acc0);
    float2 a1 = unpack2(acc1);
    *(float2*)&g_h1[node * O1 + 2 * lane] =
        make_float2(elu_f((a0.x + a1.x) * inv), elu_f((a0.y + a1.y) * inv));
}

// ========= K4c: GEMM2 (batched, W2 packed, f32x2) + es2/ed2 epilogue =========
#define G2_NB 64
__global__ __launch_bounds__(256) void k4c_gemm2(const float* __restrict__ a2s,
                                                 const float* __restrict__ a2d) {
    __shared__ float hs[G2_NB][O1];   // 16KB
    const int tid = threadIdx.x;
    const int lane = tid & 31;
    const int w = tid >> 5;
    const int nb0 = blockIdx.x * G2_NB;

    for (int idx = tid; idx < G2_NB * (O1 / 4); idx += 256) {
        int n = idx >> 4;
        int c = idx & 15;
        int g = nb0 + n;
        float4 v = make_float4(0.f, 0.f, 0.f, 0.f);
        if (g < NN) v = *(const float4*)&g_h1[(size_t)g * O1 + c * 4];
        *(float4*)&hs[n][c * 4] = v;
    }
    __syncthreads();

    unsigned long long acc[8][2];
#pragma unroll
    for (int n = 0; n < 8; n++) { acc[n][0] = 0ull; acc[n][1] = 0ull; }

    const int nrow = w * 8;
#pragma unroll 4
    for (int q = 0; q < O1 / 2; q += 2) {
        ulonglong2 wA = g_W2p[q * 32 + lane];
        ulonglong2 wB = g_W2p[(q + 1) * 32 + lane];
#pragma unroll
        for (int n = 0; n < 8; n++) {
            ulonglong2 xv = *(const ulonglong2*)&hs[nrow + n][2 * q];
            fma2(acc[n][0], xv.x, wA.x);
            fma2(acc[n][1], xv.x, wA.y);
            fma2(acc[n][0], xv.y, wB.x);
            fma2(acc[n][1], xv.y, wB.y);
        }
    }

    const float as0 = a2s[2 * lane], as1 = a2s[2 * lane + 1];
    const float ad0 = a2d[2 * lane], ad1 = a2d[2 * lane + 1];
#pragma unroll
    for (int n = 0; n < 8; n++) {
        int g = nb0 + w * 8 + n;
        if (g >= NN) continue;  // uniform across warp
        float2 p0 = unpack2(acc[n][0]);
        float2 p1 = unpack2(acc[n][1]);
        float o0 = p0.x + p0.y;
        float o1 = p1.x + p1.y;
        *(float2*)&g_Wh2[g * NLAB + 2 * lane] = make_float2(o0, o1);
        float ps = o0 * as0 + o1 * as1;
        float pd = o0 * ad0 + o1 * ad1;
#pragma unroll
        for (int o = 16; o; o >>= 1) {
            ps += __shfl_xor_sync(FULLM, ps, o);
            pd += __shfl_xor_sync(FULLM, pd, o);
        }
        if (lane == 0) { g_es2[g] = ps; g_ed2[g] = pd; }
    }
}

// ====== K5: layer-2 aggregate, batch-8 + sw-pipelined gather + softmax ======
__global__ __launch_bounds__(256) void k5_agg2(float* __restrict__ out) {
    int gid = blockIdx.x * blockDim.x + threadIdx.x;
    if (gid < NN) g_cnt[gid] = 0;   // leave cnt zeroed for the next call

    int node = gid >> 5;
    int lane = threadIdx.x & 31;
    if (node >= NN) return;
    const int beg = g_off[node], end = g_off[node + 1];
    const float ed = g_ed2[node];
    const int e8 = lane & 7;

    float sumP = 0.f;
    unsigned long long acc0 = 0ull, acc1 = 0ull;

    // depth-2 pipeline on the ssrc -> es2 gather chain (pads make loads safe)
    int   s_l = g_ssrc[beg + e8];
    float v_l = g_es2[s_l];
    for (int base = beg; base < end; base += 8) {
        int   s_n = g_ssrc[base + 8 + e8];
        float v_n = g_es2[s_n];

        const int m = end - base;
        float p_l = (e8 < m) ? __expf(lrelu_f(v_l + ed)) : 0.f;
        if (lane < 8) sumP += p_l;   // lanes 8-31 hold duplicates
#pragma unroll
        for (int j = 0; j < 8; j++) {
            int s   = __shfl_sync(FULLM, s_l, j);
            float p = __shfl_sync(FULLM, p_l, j);
            unsigned long long w2 = *(const unsigned long long*)
                &g_Wh2[s * NLAB + 2 * lane];
            if (j & 1) fma2(acc1, pack2(p, p), w2);
            else       fma2(acc0, pack2(p, p), w2);
        }
        s_l = s_n; v_l = v_n;
    }
#pragma unroll
    for (int o = 16; o; o >>= 1) sumP += __shfl_xor_sync(FULLM, sumP, o);

    const float inv = 1.f / (sumP + 1e-10f);
    float2 a0 = unpack2(acc0);
    float2 a1 = unpack2(acc1);
    float o0 = (a0.x + a1.x) * inv;
    float o1 = (a0.y + a1.y) * inv;

    // head-mean is identity (H2=1); fused softmax over 64 classes
    float m2 = fmaxf(o0, o1);
#pragma unroll
    for (int o = 16; o; o >>= 1) m2 = fmaxf(m2, __shfl_xor_sync(FULLM, m2, o));
    float e0 = __expf(o0 - m2);
    float e1 = __expf(o1 - m2);
    float s2 = e0 + e1;
#pragma unroll
    for (int o = 16; o; o >>= 1) s2 += __shfl_xor_sync(FULLM, s2, o);
    float r = 1.f / s2;
    *(float2*)&out[(size_t)node * NLAB + 2 * lane] = make_float2(e0 * r, e1 * r);
}

// ---------------- launch: fork/join — chain A (edge prep) ∥ chain B (dense) ----------------
extern "C" void kernel_launch(void* const* d_in, const int* in_sizes, int n_in,
                              void* d_out, int out_size) {
    const float* x    = (const float*)d_in[0];
    const float* W1   = (const float*)d_in[1];
    const float* a1s  = (const float*)d_in[2];
    const float* a1d  = (const float*)d_in[3];
    const float* W2   = (const float*)d_in[4];
    const float* a2s  = (const float*)d_in[5];
    const float* a2d  = (const float*)d_in[6];
    const int*   src  = (const int*)d_in[7];
    const int*   dst  = (const int*)d_in[8];
    float* out = (float*)d_out;

    // one-time host-side resources (no device memory; identical work every call)
    static cudaStream_t sB = nullptr;
    static cudaEvent_t evFork = nullptr, evJoin = nullptr;
    if (sB == nullptr) {
        cudaStreamCreateWithFlags(&sB, cudaStreamNonBlocking);
        cudaEventCreateWithFlags(&evFork, cudaEventDisableTiming);
        cudaEventCreateWithFlags(&evJoin, cudaEventDisableTiming);
    }

    // fork: bring side stream into the same dependency chain / capture graph
    cudaEventRecord(evFork, 0);
    cudaStreamWaitEvent(sB, evFork, 0);

    // chain B (side stream): weight pack -> gemm1 (+es1/ed1)
    kpack<<<36, 256, 0, sB>>>(W1, W2);
    k2_gemm1<<<(NN + G1_NB - 1) / G1_NB, 256, 0, sB>>>(x, a1s, a1d);

    // chain A (main stream): hist -> 3-phase scan -> scatter
    khist<<<HIST4_BLKS, 256>>>(dst);
    kscan_a<<<SCAN_BLKS, 256>>>();
    kscan_b<<<1, 256>>>();
    kscan_c<<<SCAN_BLKS, 256>>>();
    k3_scatter<<<HIST4_BLKS, 256>>>(src, dst);

    // join
    cudaEventRecord(evJoin, sB);
    cudaStreamWaitEvent(0, evJoin, 0);

    // serial tail
    k4_agg1<<<(NN * 32 + 255) / 256, 256>>>();
    k4c_gemm2<<<(NN + G2_NB - 1) / G2_NB, 256>>>(a2s, a2d);
    k5_agg2<<<(NN * 32 + 255) / 256, 256>>>(out);
}

// round 14
// speedup vs baseline: 1.4604x; 1.1869x over previous
#include <cuda_runtime.h>
#include <cuda_bf16.h>
#include <math.h>
#include <stdint.h>

// ---------------- problem constants ----------------
#define NN 50000
#define EE 800000
#define F_IN 512
#define H1 8
#define F_HID 8
#define O1 64          // H1*F_HID
#define NLAB 64
#define LRELU 0.2f

#define FULLM 0xffffffffu
#define SCAN_BLKS ((NN + 255) / 256)   // 196

// ---------------- device scratch (no allocs allowed) ----------------
__device__ uint2 g_Wfhi[32 * 8 * 32];          // W1 hi bf16, mma B-fragment layout
__device__ uint2 g_Wflo[32 * 8 * 32];          // W1 lo bf16 (residual)
__device__ ulonglong2 g_W2p[(O1 / 2) * 32];    // W2 packed f32x2 (gemm2)
__device__ float g_Wh1[(size_t)NN * O1];       // layer-1 node features
__device__ float g_es1[NN * H1];
__device__ float g_ed1[NN * H1];
__device__ float g_h1[(size_t)NN * O1];        // post-aggregation, post-ELU
__device__ float g_Wh2[(size_t)NN * NLAB];
__device__ float g_es2[NN];
__device__ float g_ed2[NN];
__device__ int   g_cnt[NN];                    // zero at entry (re-zeroed at tail of k5)
__device__ int   g_rank[EE];
__device__ int   g_off[NN + 1];
__device__ int   g_bsum[256];
__device__ int   g_bscan[256];
__device__ int   g_ssrc[EE + 64];              // +pad (zero-init) for unguarded pipelined loads

// ---------------- helpers ----------------
__device__ __forceinline__ unsigned long long pack2(float lo, float hi) {
    unsigned long long r;
    asm("mov.b64 %0, {%1, %2};" : "=l"(r) : "f"(lo), "f"(hi));
    return r;
}
__device__ __forceinline__ void fma2(unsigned long long& acc, unsigned long long a,
                                     unsigned long long b) {
    asm("fma.rn.f32x2 %0, %1, %2, %0;" : "+l"(acc) : "l"(a), "l"(b));
}
__device__ __forceinline__ float2 unpack2(unsigned long long v) {
    float lo, hi;
    asm("mov.b64 {%0, %1}, %2;" : "=f"(lo), "=f"(hi) : "l"(v));
    return make_float2(lo, hi);
}
__device__ __forceinline__ float lrelu_f(float v) { return fmaxf(v, LRELU * v); }
__device__ __forceinline__ float elu_f(float v)   { return v > 0.f ? v : __expf(v) - 1.f; }

__device__ __forceinline__ void mma_bf16(float* c, uint32_t a0, uint32_t a1,
                                         uint32_t a2, uint32_t a3,
                                         uint32_t b0, uint32_t b1) {
    asm volatile(
        "mma.sync.aligned.m16n8k16.row.col.f32.bf16.bf16.f32 "
        "{%0,%1,%2,%3}, {%4,%5,%6,%7}, {%8,%9}, {%0,%1,%2,%3};"
        : "+f"(c[0]), "+f"(c[1]), "+f"(c[2]), "+f"(c[3])
        : "r"(a0), "r"(a1), "r"(a2), "r"(a3), "r"(b0), "r"(b1));
}
__device__ __forceinline__ unsigned short bf16_bits(float v) {
    __nv_bfloat16 b = __float2bfloat16_rn(v);
    return *reinterpret_cast<unsigned short*>(&b);
}

// ===== KP: pack W1 into bf16 hi/lo B-fragments (64 blk) + pack W2 (4 blk) [chain B] =====
__global__ __launch_bounds__(256) void kpack(const float* __restrict__ W1,
                                             const float* __restrict__ W2) {
    const int bid = blockIdx.x;
    const int tid = threadIdx.x;
    if (bid < 64) {
        int i = bid * 256 + tid;        // 0..16383
        int term = i >> 13;             // 0 = hi, 1 = lo
        int r = i & 8191;
        int ks = r >> 8;                // 0..31 (k16 step)
        int nt = (r >> 5) & 7;          // 0..7  (n8 tile)
        int t  = r & 31;                // lane
        int k0 = ks * 16 + (t & 3) * 2;
        int n  = nt * 8 + (t >> 2);
        // W1(k, o=n) at (n>>3)*4096 + k*8 + (n&7)
        const int base = (n >> 3) * (F_IN * F_HID) + (n & 7);
        float w00 = W1[base + k0 * F_HID];
        float w01 = W1[base + (k0 + 1) * F_HID];
        float w08 = W1[base + (k0 + 8) * F_HID];
        float w09 = W1[base + (k0 + 9) * F_HID];
        unsigned short h00 = bf16_bits(w00), h01 = bf16_bits(w01);
        unsigned short h08 = bf16_bits(w08), h09 = bf16_bits(w09);
        uint2 v;
        if (term == 0) {
            v.x = (uint32_t)h00 | ((uint32_t)h01 << 16);
            v.y = (uint32_t)h08 | ((uint32_t)h09 << 16);
            g_Wfhi[(ks * 8 + nt) * 32 + t] = v;
        } else {
            __nv_bfloat16 b00 = __float2bfloat16_rn(w00), b01 = __float2bfloat16_rn(w01);
            __nv_bfloat16 b08 = __float2bfloat16_rn(w08), b09 = __float2bfloat16_rn(w09);
            unsigned short l00 = bf16_bits(w00 - __bfloat162float(b00));
            unsigned short l01 = bf16_bits(w01 - __bfloat162float(b01));
            unsigned short l08 = bf16_bits(w08 - __bfloat162float(b08));
            unsigned short l09 = bf16_bits(w09 - __bfloat162float(b09));
            v.x = (uint32_t)l00 | ((uint32_t)l01 << 16);
            v.y = (uint32_t)l08 | ((uint32_t)l09 << 16);
            g_Wflo[(ks * 8 + nt) * 32 + t] = v;
        }
    } else {
        int i = (bid - 64) * 256 + tid;   // < 1024 = (O1/2)*32
        int p = i >> 5, l = i & 31;
        int o0 = 2 * l, o1 = 2 * l + 1;
        int k0 = 2 * p, k1 = 2 * p + 1;
        ulonglong2 v;
        v.x = pack2(W2[k0 * NLAB + o0], W2[k1 * NLAB + o0]);
        v.y = pack2(W2[k0 * NLAB + o1], W2[k1 * NLAB + o1]);
        g_W2p[i] = v;
    }
}

// ================= KH: hist ×4 vectorized (rank-storing)  [chain A] =================
#define HIST4_BLKS ((EE + 1023) / 1024)
__global__ __launch_bounds__(256) void khist(const int* __restrict__ dst) {
    int e = (blockIdx.x * blockDim.x + threadIdx.x) * 4;
    if (e + 3 < EE) {
        int4 d4 = *(const int4*)&dst[e];
        int4 r4;
        r4.x = atomicAdd(&g_cnt[d4.x], 1);
        r4.y = atomicAdd(&g_cnt[d4.y], 1);
        r4.z = atomicAdd(&g_cnt[d4.z], 1);
        r4.w = atomicAdd(&g_cnt[d4.w], 1);
        *(int4*)&g_rank[e] = r4;
    } else {
        for (int q = e; q < EE; q++) g_rank[q] = atomicAdd(&g_cnt[dst[q]], 1);
    }
}

// ---- block-local inclusive scan helper (256 threads) ----
__device__ __forceinline__ int block_scan_incl_256(int v, int tid, int* wsum) {
    const int lane = tid & 31, wid = tid >> 5;
    int x = v;
#pragma unroll
    for (int d = 1; d < 32; d <<= 1) {
        int y = __shfl_up_sync(FULLM, x, d);
        if (lane >= d) x += y;
    }
    if (lane == 31) wsum[wid] = x;
    __syncthreads();
    if (wid == 0) {
        int s = (lane < 8) ? wsum[lane] : 0;
#pragma unroll
        for (int d = 1; d < 8; d <<= 1) {
            int y = __shfl_up_sync(FULLM, s, d);
            if (lane >= d) s += y;
        }
        if (lane < 8) wsum[lane] = s;
    }
    __syncthreads();
    return x + (wid ? wsum[wid - 1] : 0);
}

__global__ __launch_bounds__(256) void kscan_a() {
    __shared__ int wsum[8];
    const int b = blockIdx.x, t = threadIdx.x;
    const int i = b * 256 + t;
    int v = (i < NN) ? g_cnt[i] : 0;
    int incl = block_scan_incl_256(v, t, wsum);
    if (i < NN) g_off[i] = incl - v;
    if (t == 255) g_bsum[b] = incl;
}

__global__ __launch_bounds__(256) void kscan_b() {
    __shared__ int wsum[8];
    const int t = threadIdx.x;
    int v = (t < SCAN_BLKS) ? g_bsum[t] : 0;
    int incl = block_scan_incl_256(v, t, wsum);
    g_bscan[t] = incl - v;
    if (t == 255) g_off[NN] = incl;
}

__global__ __launch_bounds__(256) void kscan_c() {
    const int b = blockIdx.x, t = threadIdx.x;
    const int i = b * 256 + t;
    if (i < NN) g_off[i] += g_bscan[b];
}

// ===== K2: gemm1 via bf16 mma (2-term split: hihi + hilo + lohi) + es1/ed1 [chain B] =====
#define G1M 128   // node rows per block
__global__ __launch_bounds__(256) void k2_gemm1(const float* __restrict__ x,
                                                const float* __restrict__ a1s,
                                                const float* __restrict__ a1d) {
    __shared__ unsigned short xh[G1M][72];   // stride 72: conflict-free A-frag LDS
    __shared__ unsigned short xl[G1M][72];
    const int tid = threadIdx.x;
    const int lane = tid & 31;
    const int w = tid >> 5;
    const int nb0 = blockIdx.x * G1M;
    const int wr0 = w * 16 + (lane >> 2);    // block-local row for c0/c1
    const int kk0 = (lane & 3) * 2;

    float acc[8][4];
#pragma unroll
    for (int nt = 0; nt < 8; nt++)
#pragma unroll
        for (int q = 0; q < 4; q++) acc[nt][q] = 0.f;

    for (int kt = 0; kt < F_IN; kt += 64) {
        __syncthreads();
        // stage + split x[nb0..+127][kt..kt+63] -> bf16 hi/lo
        for (int it = tid; it < G1M * 16; it += 256) {
            int rrow = it >> 4, c4 = it & 15;
            int g = nb0 + rrow;
            float4 v = make_float4(0.f, 0.f, 0.f, 0.f);
            if (g < NN) v = *(const float4*)&x[(size_t)g * F_IN + kt + c4 * 4];
            __nv_bfloat162 h01 = __float22bfloat162_rn(make_float2(v.x, v.y));
            __nv_bfloat162 h23 = __float22bfloat162_rn(make_float2(v.z, v.w));
            float2 f01 = __bfloat1622float2(h01);
            float2 f23 = __bfloat1622float2(h23);
            __nv_bfloat162 l01 = __float22bfloat162_rn(make_float2(v.x - f01.x, v.y - f01.y));
            __nv_bfloat162 l23 = __float22bfloat162_rn(make_float2(v.z - f23.x, v.w - f23.y));
            uint2 hv, lv;
            hv.x = *reinterpret_cast<uint32_t*>(&h01);
            hv.y = *reinterpret_cast<uint32_t*>(&h23);
            lv.x = *reinterpret_cast<uint32_t*>(&l01);
            lv.y = *reinterpret_cast<uint32_t*>(&l23);
            *(uint2*)&xh[rrow][c4 * 4] = hv;
            *(uint2*)&xl[rrow][c4 * 4] = lv;
        }
        __syncthreads();

#pragma unroll
        for (int s = 0; s < 4; s++) {
            const int kk = s * 16 + kk0;
            uint32_t ah0 = *(const uint32_t*)&xh[wr0][kk];
            uint32_t ah1 = *(const uint32_t*)&xh[wr0 + 8][kk];
            uint32_t ah2 = *(const uint32_t*)&xh[wr0][kk + 8];
            uint32_t ah3 = *(const uint32_t*)&xh[wr0 + 8][kk + 8];
            uint32_t al0 = *(const uint32_t*)&xl[wr0][kk];
            uint32_t al1 = *(const uint32_t*)&xl[wr0 + 8][kk];
            uint32_t al2 = *(const uint32_t*)&xl[wr0][kk + 8];
            uint32_t al3 = *(const uint32_t*)&xl[wr0 + 8][kk + 8];
            const int ksbase = ((kt >> 4) + s) * 8;
#pragma unroll
            for (int nt = 0; nt < 8; nt++) {
                uint2 bh = g_Wfhi[(ksbase + nt) * 32 + lane];
                uint2 bl = g_Wflo[(ksbase + nt) * 32 + lane];
                mma_bf16(acc[nt], ah0, ah1, ah2, ah3, bh.x, bh.y);
                mma_bf16(acc[nt], ah0, ah1, ah2, ah3, bl.x, bl.y);
                mma_bf16(acc[nt], al0, al1, al2, al3, bh.x, bh.y);
            }
        }
    }

    // epilogue: store Wh1 + per-head es1/ed1 (head == nt)
    const int g0 = nb0 + wr0;
    const int g1 = g0 + 8;
    const float2* a1s2 = (const float2*)a1s;
    const float2* a1d2 = (const float2*)a1d;
#pragma unroll
    for (int nt = 0; nt < 8; nt++) {
        int col = nt * 8 + kk0;
        float2 as = __ldg(&a1s2[col >> 1]);
        float2 ad = __ldg(&a1d2[col >> 1]);
        float c0 = acc[nt][0], c1 = acc[nt][1], c2 = acc[nt][2], c3 = acc[nt][3];
        if (g0 < NN) *(float2*)&g_Wh1[(size_t)g0 * O1 + col] = make_float2(c0, c1);
        if (g1 < NN) *(float2*)&g_Wh1[(size_t)g1 * O1 + col] = make_float2(c2, c3);
        float ps0 = c0 * as.x + c1 * as.y;
        float pd0 = c0 * ad.x + c1 * ad.y;
        float ps1 = c2 * as.x + c3 * as.y;
        float pd1 = c2 * ad.x + c3 * ad.y;
        ps0 += __shfl_xor_sync(FULLM, ps0, 1); ps0 += __shfl_xor_sync(FULLM, ps0, 2);
        pd0 += __shfl_xor_sync(FULLM, pd0, 1); pd0 += __shfl_xor_sync(FULLM, pd0, 2);
        ps1 += __shfl_xor_sync(FULLM, ps1, 1); ps1 += __shfl_xor_sync(FULLM, ps1, 2);
        pd1 += __shfl_xor_sync(FULLM, pd1, 1); pd1 += __shfl_xor_sync(FULLM, pd1, 2);
        if ((lane & 3) == 0) {
            if (g0 < NN) { g_es1[g0 * H1 + nt] = ps0; g_ed1[g0 * H1 + nt] = pd0; }
            if (g1 < NN) { g_es1[g1 * H1 + nt] = ps1; g_ed1[g1 * H1 + nt] = pd1; }
        }
    }
}

// ============ K3: pure scatter (atomic-free, rank-based), ×4  [chain A] ============
__global__ void k3_scatter(const int* __restrict__ src, const int* __restrict__ dst) {
    int e = (blockIdx.x * blockDim.x + threadIdx.x) * 4;
    if (e + 3 < EE) {
        int4 d4 = *(const int4*)&dst[e];
        int4 s4 = *(const int4*)&src[e];
        int4 r4 = *(const int4*)&g_rank[e];
        g_ssrc[g_off[d4.x] + r4.x] = s4.x;
        g_ssrc[g_off[d4.y] + r4.y] = s4.y;
        g_ssrc[g_off[d4.z] + r4.z] = s4.z;
        g_ssrc[g_off[d4.w] + r4.w] = s4.w;
    } else {
        for (int q = e; q < EE; q++) g_ssrc[g_off[dst[q]] + g_rank[q]] = src[q];
    }
}

// ====== K4: layer-1 aggregate, batch-8, inline p (pipelined es1 gather) + ELU ======
__global__ __launch_bounds__(256) void k4_agg1() {
    int node = (blockIdx.x * blockDim.x + threadIdx.x) >> 5;
    int lane = threadIdx.x & 31;
    if (node >= NN) return;
    const int beg = g_off[node], end = g_off[node + 1];
    const int srcg = lane & 0x1C;
    const int e4 = lane & 3;
    const int e8 = lane & 7;
    const int h = lane >> 2;
    const float edh = g_ed1[node * H1 + h];

    int   s_l = g_ssrc[beg + e8];
    int   sA  = __shfl_sync(FULLM, s_l, e4);
    int   sB  = __shfl_sync(FULLM, s_l, 4 + e4);
    float esA = g_es1[sA * H1 + h];
    float esB = g_es1[sB * H1 + h];

    float sumP = 0.f;
    unsigned long long acc0 = 0ull, acc1 = 0ull;
    for (int base = beg; base < end; base += 8) {
        int   s_n  = g_ssrc[base + 8 + e8];
        int   sAn  = __shfl_sync(FULLM, s_n, e4);
        int   sBn  = __shfl_sync(FULLM, s_n, 4 + e4);
        float esAn = g_es1[sAn * H1 + h];
        float esBn = g_es1[sBn * H1 + h];

        const int m = end - base;
        float pA = (e4 < m)     ? __expf(lrelu_f(esA + edh)) : 0.f;
        float pB = (4 + e4 < m) ? __expf(lrelu_f(esB + edh)) : 0.f;
        sumP += pA + pB;
#pragma unroll
        for (int j = 0; j < 8; j++) {
            int s   = __shfl_sync(FULLM, s_l, j);
            float p = __shfl_sync(FULLM, (j < 4) ? pA : pB, srcg | (j & 3));
            unsigned long long w2 = *(const unsigned long long*)
                &g_Wh1[s * O1 + 2 * lane];
            if (j & 1) fma2(acc1, pack2(p, p), w2);
            else       fma2(acc0, pack2(p, p), w2);
        }
        s_l = s_n; esA = esAn; esB = esBn;
    }
    sumP += __shfl_xor_sync(FULLM, sumP, 1);
    sumP += __shfl_xor_sync(FULLM, sumP, 2);

    const float inv = 1.f / (sumP + 1e-10f);
    float2 a0 = unpack2(acc0);
    float2 a1 = unpack2(acc1);
    *(float2*)&g_h1[node * O1 + 2 * lane] =
        make_float2(elu_f((a0.x + a1.x) * inv), elu_f((a0.y + a1.y) * inv));
}

// ========= K4c: GEMM2 (batched, W2 packed, f32x2) + es2/ed2 epilogue =========
#define G2_NB 64
__global__ __launch_bounds__(256) void k4c_gemm2(const float* __restrict__ a2s,
                                                 const float* __restrict__ a2d) {
    __shared__ float hs[G2_NB][O1];   // 16KB
    const int tid = threadIdx.x;
    const int lane = tid & 31;
    const int w = tid >> 5;
    const int nb0 = blockIdx.x * G2_NB;

    for (int idx = tid; idx < G2_NB * (O1 / 4); idx += 256) {
        int n = idx >> 4;
        int c = idx & 15;
        int g = nb0 + n;
        float4 v = make_float4(0.f, 0.f, 0.f, 0.f);
        if (g < NN) v = *(const float4*)&g_h1[(size_t)g * O1 + c * 4];
        *(float4*)&hs[n][c * 4] = v;
    }
    __syncthreads();

    unsigned long long acc[8][2];
#pragma unroll
    for (int n = 0; n < 8; n++) { acc[n][0] = 0ull; acc[n][1] = 0ull; }

    const int nrow = w * 8;
#pragma unroll 4
    for (int q = 0; q < O1 / 2; q += 2) {
        ulonglong2 wA = g_W2p[q * 32 + lane];
        ulonglong2 wB = g_W2p[(q + 1) * 32 + lane];
#pragma unroll
        for (int n = 0; n < 8; n++) {
            ulonglong2 xv = *(const ulonglong2*)&hs[nrow + n][2 * q];
            fma2(acc[n][0], xv.x, wA.x);
            fma2(acc[n][1], xv.x, wA.y);
            fma2(acc[n][0], xv.y, wB.x);
            fma2(acc[n][1], xv.y, wB.y);
        }
    }

    const float as0 = a2s[2 * lane], as1 = a2s[2 * lane + 1];
    const float ad0 = a2d[2 * lane], ad1 = a2d[2 * lane + 1];
#pragma unroll
    for (int n = 0; n < 8; n++) {
        int g = nb0 + w * 8 + n;
        if (g >= NN) continue;
        float2 p0 = unpack2(acc[n][0]);
        float2 p1 = unpack2(acc[n][1]);
        float o0 = p0.x + p0.y;
        float o1 = p1.x + p1.y;
        *(float2*)&g_Wh2[g * NLAB + 2 * lane] = make_float2(o0, o1);
        float ps = o0 * as0 + o1 * as1;
        float pd = o0 * ad0 + o1 * ad1;
#pragma unroll
        for (int o = 16; o; o >>= 1) {
            ps += __shfl_xor_sync(FULLM, ps, o);
            pd += __shfl_xor_sync(FULLM, pd, o);
        }
        if (lane == 0) { g_es2[g] = ps; g_ed2[g] = pd; }
    }
}

// ====== K5: layer-2 aggregate, batch-8 + sw-pipelined gather + softmax ======
__global__ __launch_bounds__(256) void k5_agg2(float* __restrict__ out) {
    int gid = blockIdx.x * blockDim.x + threadIdx.x;
    if (gid < NN) g_cnt[gid] = 0;

    int node = gid >> 5;
    int lane = threadIdx.x & 31;
    if (node >= NN) return;
    const int beg = g_off[node], end = g_off[node + 1];
    const float ed = g_ed2[node];
    const int e8 = lane & 7;

    float sumP = 0.f;
    unsigned long long acc0 = 0ull, acc1 = 0ull;

    int   s_l = g_ssrc[beg + e8];
    float v_l = g_es2[s_l];
    for (int base = beg; base < end; base += 8) {
        int   s_n = g_ssrc[base + 8 + e8];
        float v_n = g_es2[s_n];

        const int m = end - base;
        float p_l = (e8 < m) ? __expf(lrelu_f(v_l + ed)) : 0.f;
        if (lane < 8) sumP += p_l;
#pragma unroll
        for (int j = 0; j < 8; j++) {
            int s   = __shfl_sync(FULLM, s_l, j);
            float p = __shfl_sync(FULLM, p_l, j);
            unsigned long long w2 = *(const unsigned long long*)
                &g_Wh2[s * NLAB + 2 * lane];
            if (j & 1) fma2(acc1, pack2(p, p), w2);
            else       fma2(acc0, pack2(p, p), w2);
        }
        s_l = s_n; v_l = v_n;
    }
#pragma unroll
    for (int o = 16; o; o >>= 1) sumP += __shfl_xor_sync(FULLM, sumP, o);

    const float inv = 1.f / (sumP + 1e-10f);
    float2 a0 = unpack2(acc0);
    float2 a1 = unpack2(acc1);
    float o0 = (a0.x + a1.x) * inv;
    float o1 = (a0.y + a1.y) * inv;

    float m2 = fmaxf(o0, o1);
#pragma unroll
    for (int o = 16; o; o >>= 1) m2 = fmaxf(m2, __shfl_xor_sync(FULLM, m2, o));
    float e0 = __expf(o0 - m2);
    float e1 = __expf(o1 - m2);
    float s2 = e0 + e1;
#pragma unroll
    for (int o = 16; o; o >>= 1) s2 += __shfl_xor_sync(FULLM, s2, o);
    float r = 1.f / s2;
    *(float2*)&out[(size_t)node * NLAB + 2 * lane] = make_float2(e0 * r, e1 * r);
}

// ---------------- launch: fork/join — chain A (edge prep) ∥ chain B (dense) ----------------
extern "C" void kernel_launch(void* const* d_in, const int* in_sizes, int n_in,
                              void* d_out, int out_size) {
    const float* x    = (const float*)d_in[0];
    const float* W1   = (const float*)d_in[1];
    const float* a1s  = (const float*)d_in[2];
    const float* a1d  = (const float*)d_in[3];
    const float* W2   = (const float*)d_in[4];
    const float* a2s  = (const float*)d_in[5];
    const float* a2d  = (const float*)d_in[6];
    const int*   src  = (const int*)d_in[7];
    const int*   dst  = (const int*)d_in[8];
    float* out = (float*)d_out;

    static cudaStream_t sB = nullptr;
    static cudaEvent_t evFork = nullptr, evJoin = nullptr;
    if (sB == nullptr) {
        cudaStreamCreateWithFlags(&sB, cudaStreamNonBlocking);
        cudaEventCreateWithFlags(&evFork, cudaEventDisableTiming);
        cudaEventCreateWithFlags(&evJoin, cudaEventDisableTiming);
    }

    cudaEventRecord(evFork, 0);
    cudaStreamWaitEvent(sB, evFork, 0);

    // chain B (side stream): weight pack -> mma gemm1 (+es1/ed1)
    kpack<<<68, 256, 0, sB>>>(W1, W2);
    k2_gemm1<<<(NN + G1M - 1) / G1M, 256, 0, sB>>>(x, a1s, a1d);

    // chain A (main stream): hist -> 3-phase scan -> scatter
    khist<<<HIST4_BLKS, 256>>>(dst);
    kscan_a<<<SCAN_BLKS, 256>>>();
    kscan_b<<<1, 256>>>();
    kscan_c<<<SCAN_BLKS, 256>>>();
    k3_scatter<<<HIST4_BLKS, 256>>>(src, dst);

    // join
    cudaEventRecord(evJoin, sB);
    cudaStreamWaitEvent(0, evJoin, 0);

    // serial tail
    k4_agg1<<<(NN * 32 + 255) / 256, 256>>>();
    k4c_gemm2<<<(NN + G2_NB - 1) / G2_NB, 256>>>(a2s, a2d);
    k5_agg2<<<(NN * 32 + 255) / 256, 256>>>(out);
}

// round 15
// speedup vs baseline: 1.4701x; 1.0067x over previous
#include <cuda_runtime.h>
#include <cuda_bf16.h>
#include <math.h>
#include <stdint.h>

// ---------------- problem constants ----------------
#define NN 50000
#define EE 800000
#define F_IN 512
#define H1 8
#define F_HID 8
#define O1 64          // H1*F_HID
#define NLAB 64
#define LRELU 0.2f

#define FULLM 0xffffffffu
#define SCAN_BLKS ((NN + 255) / 256)   // 196

// ---------------- device scratch (no allocs allowed) ----------------
__device__ uint2 g_Wfhi[32 * 8 * 32];          // W1 hi bf16, mma B-fragment layout
__device__ uint2 g_Wflo[32 * 8 * 32];          // W1 lo bf16 (residual)
__device__ ulonglong2 g_W2p[(O1 / 2) * 32];    // W2 packed f32x2 (gemm2)
__device__ float g_Wh1[(size_t)NN * O1];       // layer-1 node features
__device__ float g_es1[NN * H1];
__device__ float g_ed1[NN * H1];
__device__ float g_h1[(size_t)NN * O1];        // post-aggregation, post-ELU
__device__ float g_Wh2[(size_t)NN * NLAB];
__device__ float g_es2[NN];
__device__ float g_ed2[NN];
__device__ int   g_cnt[NN];                    // zero at entry (re-zeroed at tail of k5)
__device__ int   g_rank[EE];
__device__ int   g_off[NN + 1];
__device__ int   g_bsum[256];
__device__ int   g_bscan[256];
__device__ int   g_ssrc[EE + 64];              // +pad (zero-init) for unguarded batch loads

// ---------------- helpers ----------------
__device__ __forceinline__ unsigned long long pack2(float lo, float hi) {
    unsigned long long r;
    asm("mov.b64 %0, {%1, %2};" : "=l"(r) : "f"(lo), "f"(hi));
    return r;
}
__device__ __forceinline__ void fma2(unsigned long long& acc, unsigned long long a,
                                     unsigned long long b) {
    asm("fma.rn.f32x2 %0, %1, %2, %0;" : "+l"(acc) : "l"(a), "l"(b));
}
__device__ __forceinline__ float2 unpack2(unsigned long long v) {
    float lo, hi;
    asm("mov.b64 {%0, %1}, %2;" : "=f"(lo), "=f"(hi) : "l"(v));
    return make_float2(lo, hi);
}
__device__ __forceinline__ float lrelu_f(float v) { return fmaxf(v, LRELU * v); }
__device__ __forceinline__ float elu_f(float v)   { return v > 0.f ? v : __expf(v) - 1.f; }

__device__ __forceinline__ void mma_bf16(float* c, uint32_t a0, uint32_t a1,
                                         uint32_t a2, uint32_t a3,
                                         uint32_t b0, uint32_t b1) {
    asm volatile(
        "mma.sync.aligned.m16n8k16.row.col.f32.bf16.bf16.f32 "
        "{%0,%1,%2,%3}, {%4,%5,%6,%7}, {%8,%9}, {%0,%1,%2,%3};"
        : "+f"(c[0]), "+f"(c[1]), "+f"(c[2]), "+f"(c[3])
        : "r"(a0), "r"(a1), "r"(a2), "r"(a3), "r"(b0), "r"(b1));
}
__device__ __forceinline__ unsigned short bf16_bits(float v) {
    __nv_bfloat16 b = __float2bfloat16_rn(v);
    return *reinterpret_cast<unsigned short*>(&b);
}

// ===== KP: pack W1 into bf16 hi/lo B-fragments (64 blk) + pack W2 (4 blk) [chain B] =====
__global__ __launch_bounds__(256) void kpack(const float* __restrict__ W1,
                                             const float* __restrict__ W2) {
    const int bid = blockIdx.x;
    const int tid = threadIdx.x;
    if (bid < 64) {
        int i = bid * 256 + tid;        // 0..16383
        int term = i >> 13;             // 0 = hi, 1 = lo
        int r = i & 8191;
        int ks = r >> 8;                // 0..31 (k16 step)
        int nt = (r >> 5) & 7;          // 0..7  (n8 tile)
        int t  = r & 31;                // lane
        int k0 = ks * 16 + (t & 3) * 2;
        int n  = nt * 8 + (t >> 2);
        const int base = (n >> 3) * (F_IN * F_HID) + (n & 7);
        float w00 = W1[base + k0 * F_HID];
        float w01 = W1[base + (k0 + 1) * F_HID];
        float w08 = W1[base + (k0 + 8) * F_HID];
        float w09 = W1[base + (k0 + 9) * F_HID];
        uint2 v;
        if (term == 0) {
            v.x = (uint32_t)bf16_bits(w00) | ((uint32_t)bf16_bits(w01) << 16);
            v.y = (uint32_t)bf16_bits(w08) | ((uint32_t)bf16_bits(w09) << 16);
            g_Wfhi[(ks * 8 + nt) * 32 + t] = v;
        } else {
            __nv_bfloat16 b00 = __float2bfloat16_rn(w00), b01 = __float2bfloat16_rn(w01);
            __nv_bfloat16 b08 = __float2bfloat16_rn(w08), b09 = __float2bfloat16_rn(w09);
            unsigned short l00 = bf16_bits(w00 - __bfloat162float(b00));
            unsigned short l01 = bf16_bits(w01 - __bfloat162float(b01));
            unsigned short l08 = bf16_bits(w08 - __bfloat162float(b08));
            unsigned short l09 = bf16_bits(w09 - __bfloat162float(b09));
            v.x = (uint32_t)l00 | ((uint32_t)l01 << 16);
            v.y = (uint32_t)l08 | ((uint32_t)l09 << 16);
            g_Wflo[(ks * 8 + nt) * 32 + t] = v;
        }
    } else {
        int i = (bid - 64) * 256 + tid;   // < 1024 = (O1/2)*32
        int p = i >> 5, l = i & 31;
        int o0 = 2 * l, o1 = 2 * l + 1;
        int k0 = 2 * p, k1 = 2 * p + 1;
        ulonglong2 v;
        v.x = pack2(W2[k0 * NLAB + o0], W2[k1 * NLAB + o0]);
        v.y = pack2(W2[k0 * NLAB + o1], W2[k1 * NLAB + o1]);
        g_W2p[i] = v;
    }
}

// ================= KH: hist ×4 vectorized (rank-storing)  [chain A] =================
#define HIST4_BLKS ((EE + 1023) / 1024)
__global__ __launch_bounds__(256) void khist(const int* __restrict__ dst) {
    int e = (blockIdx.x * blockDim.x + threadIdx.x) * 4;
    if (e + 3 < EE) {
        int4 d4 = *(const int4*)&dst[e];
        int4 r4;
        r4.x = atomicAdd(&g_cnt[d4.x], 1);
        r4.y = atomicAdd(&g_cnt[d4.y], 1);
        r4.z = atomicAdd(&g_cnt[d4.z], 1);
        r4.w = atomicAdd(&g_cnt[d4.w], 1);
        *(int4*)&g_rank[e] = r4;
    } else {
        for (int q = e; q < EE; q++) g_rank[q] = atomicAdd(&g_cnt[dst[q]], 1);
    }
}

// ---- block-local inclusive scan helper (256 threads) ----
__device__ __forceinline__ int block_scan_incl_256(int v, int tid, int* wsum) {
    const int lane = tid & 31, wid = tid >> 5;
    int x = v;
#pragma unroll
    for (int d = 1; d < 32; d <<= 1) {
        int y = __shfl_up_sync(FULLM, x, d);
        if (lane >= d) x += y;
    }
    if (lane == 31) wsum[wid] = x;
    __syncthreads();
    if (wid == 0) {
        int s = (lane < 8) ? wsum[lane] : 0;
#pragma unroll
        for (int d = 1; d < 8; d <<= 1) {
            int y = __shfl_up_sync(FULLM, s, d);
            if (lane >= d) s += y;
        }
        if (lane < 8) wsum[lane] = s;
    }
    __syncthreads();
    return x + (wid ? wsum[wid - 1] : 0);
}

__global__ __launch_bounds__(256) void kscan_a() {
    __shared__ int wsum[8];
    const int b = blockIdx.x, t = threadIdx.x;
    const int i = b * 256 + t;
    int v = (i < NN) ? g_cnt[i] : 0;
    int incl = block_scan_incl_256(v, t, wsum);
    if (i < NN) g_off[i] = incl - v;
    if (t == 255) g_bsum[b] = incl;
}

__global__ __launch_bounds__(256) void kscan_b() {
    __shared__ int wsum[8];
    const int t = threadIdx.x;
    int v = (t < SCAN_BLKS) ? g_bsum[t] : 0;
    int incl = block_scan_incl_256(v, t, wsum);
    g_bscan[t] = incl - v;
    if (t == 255) g_off[NN] = incl;
}

__global__ __launch_bounds__(256) void kscan_c() {
    const int b = blockIdx.x, t = threadIdx.x;
    const int i = b * 256 + t;
    if (i < NN) g_off[i] += g_bscan[b];
}

// ===== K2: gemm1 via bf16 mma (2-term split) + es1/ed1 epilogue  [chain B] =====
#define G1M 128   // node rows per block
__global__ __launch_bounds__(256) void k2_gemm1(const float* __restrict__ x,
                                                const float* __restrict__ a1s,
                                                const float* __restrict__ a1d) {
    __shared__ unsigned short xh[G1M][72];   // stride 72: conflict-free A-frag LDS
    __shared__ unsigned short xl[G1M][72];
    const int tid = threadIdx.x;
    const int lane = tid & 31;
    const int w = tid >> 5;
    const int nb0 = blockIdx.x * G1M;
    const int wr0 = w * 16 + (lane >> 2);
    const int kk0 = (lane & 3) * 2;

    float acc[8][4];
#pragma unroll
    for (int nt = 0; nt < 8; nt++)
#pragma unroll
        for (int q = 0; q < 4; q++) acc[nt][q] = 0.f;

    for (int kt = 0; kt < F_IN; kt += 64) {
        __syncthreads();
        for (int it = tid; it < G1M * 16; it += 256) {
            int rrow = it >> 4, c4 = it & 15;
            int g = nb0 + rrow;
            float4 v = make_float4(0.f, 0.f, 0.f, 0.f);
            if (g < NN) v = *(const float4*)&x[(size_t)g * F_IN + kt + c4 * 4];
            __nv_bfloat162 h01 = __float22bfloat162_rn(make_float2(v.x, v.y));
            __nv_bfloat162 h23 = __float22bfloat162_rn(make_float2(v.z, v.w));
            float2 f01 = __bfloat1622float2(h01);
            float2 f23 = __bfloat1622float2(h23);
            __nv_bfloat162 l01 = __float22bfloat162_rn(make_float2(v.x - f01.x, v.y - f01.y));
            __nv_bfloat162 l23 = __float22bfloat162_rn(make_float2(v.z - f23.x, v.w - f23.y));
            uint2 hv, lv;
            hv.x = *reinterpret_cast<uint32_t*>(&h01);
            hv.y = *reinterpret_cast<uint32_t*>(&h23);
            lv.x = *reinterpret_cast<uint32_t*>(&l01);
            lv.y = *reinterpret_cast<uint32_t*>(&l23);
            *(uint2*)&xh[rrow][c4 * 4] = hv;
            *(uint2*)&xl[rrow][c4 * 4] = lv;
        }
        __syncthreads();

#pragma unroll
        for (int s = 0; s < 4; s++) {
            const int kk = s * 16 + kk0;
            uint32_t ah0 = *(const uint32_t*)&xh[wr0][kk];
            uint32_t ah1 = *(const uint32_t*)&xh[wr0 + 8][kk];
            uint32_t ah2 = *(const uint32_t*)&xh[wr0][kk + 8];
            uint32_t ah3 = *(const uint32_t*)&xh[wr0 + 8][kk + 8];
            uint32_t al0 = *(const uint32_t*)&xl[wr0][kk];
            uint32_t al1 = *(const uint32_t*)&xl[wr0 + 8][kk];
            uint32_t al2 = *(const uint32_t*)&xl[wr0][kk + 8];
            uint32_t al3 = *(const uint32_t*)&xl[wr0 + 8][kk + 8];
            const int ksbase = ((kt >> 4) + s) * 8;
#pragma unroll
            for (int nt = 0; nt < 8; nt++) {
                uint2 bh = g_Wfhi[(ksbase + nt) * 32 + lane];
                uint2 bl = g_Wflo[(ksbase + nt) * 32 + lane];
                mma_bf16(acc[nt], ah0, ah1, ah2, ah3, bh.x, bh.y);
                mma_bf16(acc[nt], ah0, ah1, ah2, ah3, bl.x, bl.y);
                mma_bf16(acc[nt], al0, al1, al2, al3, bh.x, bh.y);
            }
        }
    }

    const int g0 = nb0 + wr0;
    const int g1 = g0 + 8;
    const float2* a1s2 = (const float2*)a1s;
    const float2* a1d2 = (const float2*)a1d;
#pragma unroll
    for (int nt = 0; nt < 8; nt++) {
        int col = nt * 8 + kk0;
        float2 as = __ldg(&a1s2[col >> 1]);
        float2 ad = __ldg(&a1d2[col >> 1]);
        float c0 = acc[nt][0], c1 = acc[nt][1], c2 = acc[nt][2], c3 = acc[nt][3];
        if (g0 < NN) *(float2*)&g_Wh1[(size_t)g0 * O1 + col] = make_float2(c0, c1);
        if (g1 < NN) *(float2*)&g_Wh1[(size_t)g1 * O1 + col] = make_float2(c2, c3);
        float ps0 = c0 * as.x + c1 * as.y;
        float pd0 = c0 * ad.x + c1 * ad.y;
        float ps1 = c2 * as.x + c3 * as.y;
        float pd1 = c2 * ad.x + c3 * ad.y;
        ps0 += __shfl_xor_sync(FULLM, ps0, 1); ps0 += __shfl_xor_sync(FULLM, ps0, 2);
        pd0 += __shfl_xor_sync(FULLM, pd0, 1); pd0 += __shfl_xor_sync(FULLM, pd0, 2);
        ps1 += __shfl_xor_sync(FULLM, ps1, 1); ps1 += __shfl_xor_sync(FULLM, ps1, 2);
        pd1 += __shfl_xor_sync(FULLM, pd1, 1); pd1 += __shfl_xor_sync(FULLM, pd1, 2);
        if ((lane & 3) == 0) {
            if (g0 < NN) { g_es1[g0 * H1 + nt] = ps0; g_ed1[g0 * H1 + nt] = pd0; }
            if (g1 < NN) { g_es1[g1 * H1 + nt] = ps1; g_ed1[g1 * H1 + nt] = pd1; }
        }
    }
}

// ============ K3: pure scatter (atomic-free, rank-based), ×4  [chain A] ============
__global__ void k3_scatter(const int* __restrict__ src, const int* __restrict__ dst) {
    int e = (blockIdx.x * blockDim.x + threadIdx.x) * 4;
    if (e + 3 < EE) {
        int4 d4 = *(const int4*)&dst[e];
        int4 s4 = *(const int4*)&src[e];
        int4 r4 = *(const int4*)&g_rank[e];
        g_ssrc[g_off[d4.x] + r4.x] = s4.x;
        g_ssrc[g_off[d4.y] + r4.y] = s4.y;
        g_ssrc[g_off[d4.z] + r4.z] = s4.z;
        g_ssrc[g_off[d4.w] + r4.w] = s4.w;
    } else {
        for (int q = e; q < EE; q++) g_ssrc[g_off[dst[q]] + g_rank[q]] = src[q];
    }
}

// ====== K4: layer-1 aggregate, batch-8, inline p (pipelined es1 gather) + ELU ======
__global__ __launch_bounds__(256) void k4_agg1() {
    int node = (blockIdx.x * blockDim.x + threadIdx.x) >> 5;
    int lane = threadIdx.x & 31;
    if (node >= NN) return;
    const int beg = g_off[node], end = g_off[node + 1];
    const int srcg = lane & 0x1C;
    const int e4 = lane & 3;
    const int e8 = lane & 7;
    const int h = lane >> 2;
    const float edh = g_ed1[node * H1 + h];

    int   s_l = g_ssrc[beg + e8];
    int   sA  = __shfl_sync(FULLM, s_l, e4);
    int   sB  = __shfl_sync(FULLM, s_l, 4 + e4);
    float esA = g_es1[sA * H1 + h];
    float esB = g_es1[sB * H1 + h];

    float sumP = 0.f;
    unsigned long long acc0 = 0ull, acc1 = 0ull;
    for (int base = beg; base < end; base += 8) {
        int   s_n  = g_ssrc[base + 8 + e8];
        int   sAn  = __shfl_sync(FULLM, s_n, e4);
        int   sBn  = __shfl_sync(FULLM, s_n, 4 + e4);
        float esAn = g_es1[sAn * H1 + h];
        float esBn = g_es1[sBn * H1 + h];

        const int m = end - base;
        float pA = (e4 < m)     ? __expf(lrelu_f(esA + edh)) : 0.f;
        float pB = (4 + e4 < m) ? __expf(lrelu_f(esB + edh)) : 0.f;
        sumP += pA + pB;
#pragma unroll
        for (int j = 0; j < 8; j++) {
            int s   = __shfl_sync(FULLM, s_l, j);
            float p = __shfl_sync(FULLM, (j < 4) ? pA : pB, srcg | (j & 3));
            unsigned long long w2 = *(const unsigned long long*)
                &g_Wh1[s * O1 + 2 * lane];
            if (j & 1) fma2(acc1, pack2(p, p), w2);
            else       fma2(acc0, pack2(p, p), w2);
        }
        s_l = s_n; esA = esAn; esB = esBn;
    }
    sumP += __shfl_xor_sync(FULLM, sumP, 1);
    sumP += __shfl_xor_sync(FULLM, sumP, 2);

    const float inv = 1.f / (sumP + 1e-10f);
    float2 a0 = unpack2(acc0);
    float2 a1 = unpack2(acc1);
    *(float2*)&g_h1[node * O1 + 2 * lane] =
        make_float2(elu_f((a0.x + a1.x) * inv), elu_f((a0.y + a1.y) * inv));
}

// ========= K4c: GEMM2 (batched, W2 packed, f32x2) + es2/ed2 epilogue =========
#define G2_NB 64
__global__ __launch_bounds__(256) void k4c_gemm2(const float* __restrict__ a2s,
                                                 const float* __restrict__ a2d) {
    __shared__ float hs[G2_NB][O1];   // 16KB
    const int tid = threadIdx.x;
    const int lane = tid & 31;
    const int w = tid >> 5;
    const int nb0 = blockIdx.x * G2_NB;

    for (int idx = tid; idx < G2_NB * (O1 / 4); idx += 256) {
        int n = idx >> 4;
        int c = idx & 15;
        int g = nb0 + n;
        float4 v = make_float4(0.f, 0.f, 0.f, 0.f);
        if (g < NN) v = *(const float4*)&g_h1[(size_t)g * O1 + c * 4];
        *(float4*)&hs[n][c * 4] = v;
    }
    __syncthreads();

    unsigned long long acc[8][2];
#pragma unroll
    for (int n = 0; n < 8; n++) { acc[n][0] = 0ull; acc[n][1] = 0ull; }

    const int nrow = w * 8;
#pragma unroll 4
    for (int q = 0; q < O1 / 2; q += 2) {
        ulonglong2 wA = g_W2p[q * 32 + lane];
        ulonglong2 wB = g_W2p[(q + 1) * 32 + lane];
#pragma unroll
        for (int n = 0; n < 8; n++) {
            ulonglong2 xv = *(const ulonglong2*)&hs[nrow + n][2 * q];
            fma2(acc[n][0], xv.x, wA.x);
            fma2(acc[n][1], xv.x, wA.y);
            fma2(acc[n][0], xv.y, wB.x);
            fma2(acc[n][1], xv.y, wB.y);
        }
    }

    const float as0 = a2s[2 * lane], as1 = a2s[2 * lane + 1];
    const float ad0 = a2d[2 * lane], ad1 = a2d[2 * lane + 1];
#pragma unroll
    for (int n = 0; n < 8; n++) {
        int g = nb0 + w * 8 + n;
        if (g >= NN) continue;
        float2 p0 = unpack2(acc[n][0]);
        float2 p1 = unpack2(acc[n][1]);
        float o0 = p0.x + p0.y;
        float o1 = p1.x + p1.y;
        *(float2*)&g_Wh2[g * NLAB + 2 * lane] = make_float2(o0, o1);
        float ps = o0 * as0 + o1 * as1;
        float pd = o0 * ad0 + o1 * ad1;
#pragma unroll
        for (int o = 16; o; o >>= 1) {
            ps += __shfl_xor_sync(FULLM, ps, o);
            pd += __shfl_xor_sync(FULLM, pd, o);
        }
        if (lane == 0) { g_es2[g] = ps; g_ed2[g] = pd; }
    }
}

// ====== K5: layer-2 aggregate, batch-32 per-lane staging + gated 8-sub-batches ======
__global__ __launch_bounds__(256) void k5_agg2(float* __restrict__ out) {
    int gid = blockIdx.x * blockDim.x + threadIdx.x;
    if (gid < NN) g_cnt[gid] = 0;   // leave cnt zeroed for the next call

    int node = gid >> 5;
    int lane = threadIdx.x & 31;
    if (node >= NN) return;
    const int beg = g_off[node], end = g_off[node + 1];
    const float ed = g_ed2[node];

    float sumP = 0.f;
    unsigned long long acc0 = 0ull, acc1 = 0ull;

    for (int base = beg; base < end; base += 32) {
        const int m = end - base;
        // full-warp staging: 32 edges, one s + one es2-gather + one exp per lane
        int   s_l = g_ssrc[base + lane];           // pad zero-init -> safe
        float v_l = g_es2[s_l];
        float p_l = (lane < m) ? __expf(lrelu_f(v_l + ed)) : 0.f;
        sumP += p_l;
        // consume in gated, unrolled sub-batches of 8 (waste <= 7 edges)
#pragma unroll
        for (int sb = 0; sb < 4; sb++) {
            if (sb * 8 >= m) break;
#pragma unroll
            for (int j = 0; j < 8; j++) {
                const int jj = sb * 8 + j;
                int s   = __shfl_sync(FULLM, s_l, jj);
                float p = __shfl_sync(FULLM, p_l, jj);
                unsigned long long w2 = *(const unsigned long long*)
                    &g_Wh2[s * NLAB + 2 * lane];
                if (j & 1) fma2(acc1, pack2(p, p), w2);
                else       fma2(acc0, pack2(p, p), w2);
            }
        }
    }
#pragma unroll
    for (int o = 16; o; o >>= 1) sumP += __shfl_xor_sync(FULLM, sumP, o);

    const float inv = 1.f / (sumP + 1e-10f);
    float2 a0 = unpack2(acc0);
    float2 a1 = unpack2(acc1);
    float o0 = (a0.x + a1.x) * inv;
    float o1 = (a0.y + a1.y) * inv;

    // head-mean is identity (H2=1); fused softmax over 64 classes
    float m2 = fmaxf(o0, o1);
#pragma unroll
    for (int o = 16; o; o >>= 1) m2 = fmaxf(m2, __shfl_xor_sync(FULLM, m2, o));
    float e0 = __expf(o0 - m2);
    float e1 = __expf(o1 - m2);
    float s2 = e0 + e1;
#pragma unroll
    for (int o = 16; o; o >>= 1) s2 += __shfl_xor_sync(FULLM, s2, o);
    float r = 1.f / s2;
    *(float2*)&out[(size_t)node * NLAB + 2 * lane] = make_float2(e0 * r, e1 * r);
}

// ---------------- launch: fork/join — chain A (edge prep) ∥ chain B (dense) ----------------
extern "C" void kernel_launch(void* const* d_in, const int* in_sizes, int n_in,
                              void* d_out, int out_size) {
    const float* x    = (const float*)d_in[0];
    const float* W1   = (const float*)d_in[1];
    const float* a1s  = (const float*)d_in[2];
    const float* a1d  = (const float*)d_in[3];
    const float* W2   = (const float*)d_in[4];
    const float* a2s  = (const float*)d_in[5];
    const float* a2d  = (const float*)d_in[6];
    const int*   src  = (const int*)d_in[7];
    const int*   dst  = (const int*)d_in[8];
    float* out = (float*)d_out;

    static cudaStream_t sB = nullptr;
    static cudaEvent_t evFork = nullptr, evJoin = nullptr;
    if (sB == nullptr) {
        cudaStreamCreateWithFlags(&sB, cudaStreamNonBlocking);
        cudaEventCreateWithFlags(&evFork, cudaEventDisableTiming);
        cudaEventCreateWithFlags(&evJoin, cudaEventDisableTiming);
    }

    cudaEventRecord(evFork, 0);
    cudaStreamWaitEvent(sB, evFork, 0);

    // submission order puts k2_gemm1 4th (ncu profiles the 4th launch);
    // execution order is unchanged (streams carry the real dependencies).
    kpack<<<68, 256, 0, sB>>>(W1, W2);              // 1 (chain B)
    khist<<<HIST4_BLKS, 256>>>(dst);                // 2 (chain A)
    kscan_a<<<SCAN_BLKS, 256>>>();                  // 3 (chain A)
    k2_gemm1<<<(NN + G1M - 1) / G1M, 256, 0, sB>>>(x, a1s, a1d);  // 4 (chain B)
    kscan_b<<<1, 256>>>();                          // 5 (chain A)
    kscan_c<<<SCAN_BLKS, 256>>>();                  // 6 (chain A)
    k3_scatter<<<HIST4_BLKS, 256>>>(src, dst);      // 7 (chain A)

    // join
    cudaEventRecord(evJoin, sB);
    cudaStreamWaitEvent(0, evJoin, 0);

    // serial tail
    k4_agg1<<<(NN * 32 + 255) / 256, 256>>>();
    k4c_gemm2<<<(NN + G2_NB - 1) / G2_NB, 256>>>(a2s, a2d);
    k5_agg2<<<(NN * 32 + 255) / 256, 256>>>(out);
}

// round 16
// speedup vs baseline: 1.6837x; 1.1452x over previous
#include <cuda_runtime.h>
#include <cuda_bf16.h>
#include <math.h>
#include <stdint.h>

// ---------------- problem constants ----------------
#define NN 50000
#define EE 800000
#define F_IN 512
#define H1 8
#define F_HID 8
#define O1 64          // H1*F_HID
#define NLAB 64
#define LRELU 0.2f

#define FULLM 0xffffffffu
#define SCAN_BLKS ((NN + 255) / 256)   // 196

// ---------------- device scratch (no allocs allowed) ----------------
__device__ uint2 g_Wfhi[32 * 8 * 32];          // W1 hi bf16, mma B-fragment layout
__device__ uint2 g_Wflo[32 * 8 * 32];          // W1 lo bf16 (residual)
__device__ ulonglong2 g_W2p[(O1 / 2) * 32];    // W2 packed f32x2 (gemm2)
__device__ float g_Wh1[(size_t)NN * O1];       // layer-1 node features
__device__ float g_es1[NN * H1];
__device__ float g_ed1[NN * H1];
__device__ float g_h1[(size_t)NN * O1];        // post-aggregation, post-ELU
__device__ float g_Wh2[(size_t)NN * NLAB];
__device__ float g_es2[NN];
__device__ float g_ed2[NN];
__device__ int   g_cnt[NN];                    // zero at entry (re-zeroed at tail of k5)
__device__ int   g_rank[EE];
__device__ int   g_off[NN + 1];
__device__ int   g_bsum[256];
__device__ int   g_bscan[256];
__device__ int   g_ssrc[EE + 64];              // +pad (zero-init) for unguarded batch loads

// ---------------- helpers ----------------
__device__ __forceinline__ unsigned long long pack2(float lo, float hi) {
    unsigned long long r;
    asm("mov.b64 %0, {%1, %2};" : "=l"(r) : "f"(lo), "f"(hi));
    return r;
}
__device__ __forceinline__ void fma2(unsigned long long& acc, unsigned long long a,
                                     unsigned long long b) {
    asm("fma.rn.f32x2 %0, %1, %2, %0;" : "+l"(acc) : "l"(a), "l"(b));
}
__device__ __forceinline__ float2 unpack2(unsigned long long v) {
    float lo, hi;
    asm("mov.b64 {%0, %1}, %2;" : "=f"(lo), "=f"(hi) : "l"(v));
    return make_float2(lo, hi);
}
__device__ __forceinline__ float lrelu_f(float v) { return fmaxf(v, LRELU * v); }
__device__ __forceinline__ float elu_f(float v)   { return v > 0.f ? v : __expf(v) - 1.f; }

__device__ __forceinline__ void mma_bf16(float* c, uint32_t a0, uint32_t a1,
                                         uint32_t a2, uint32_t a3,
                                         uint32_t b0, uint32_t b1) {
    asm volatile(
        "mma.sync.aligned.m16n8k16.row.col.f32.bf16.bf16.f32 "
        "{%0,%1,%2,%3}, {%4,%5,%6,%7}, {%8,%9}, {%0,%1,%2,%3};"
        : "+f"(c[0]), "+f"(c[1]), "+f"(c[2]), "+f"(c[3])
        : "r"(a0), "r"(a1), "r"(a2), "r"(a3), "r"(b0), "r"(b1));
}
__device__ __forceinline__ unsigned short bf16_bits(float v) {
    __nv_bfloat16 b = __float2bfloat16_rn(v);
    return *reinterpret_cast<unsigned short*>(&b);
}
// fp32 pair -> bf16x2 hi + bf16x2 lo (residual)
__device__ __forceinline__ void cvt_hilo(float2 v, uint32_t& hi, uint32_t& lo) {
    __nv_bfloat162 h = __float22bfloat162_rn(v);
    float2 f = __bfloat1622float2(h);
    __nv_bfloat162 l = __float22bfloat162_rn(make_float2(v.x - f.x, v.y - f.y));
    hi = *reinterpret_cast<uint32_t*>(&h);
    lo = *reinterpret_cast<uint32_t*>(&l);
}

// ===== KP: pack W1 into bf16 hi/lo B-fragments (64 blk) + pack W2 (4 blk) [chain B] =====
__global__ __launch_bounds__(256) void kpack(const float* __restrict__ W1,
                                             const float* __restrict__ W2) {
    const int bid = blockIdx.x;
    const int tid = threadIdx.x;
    if (bid < 64) {
        int i = bid * 256 + tid;        // 0..16383
        int term = i >> 13;             // 0 = hi, 1 = lo
        int r = i & 8191;
        int ks = r >> 8;                // 0..31 (k16 step)
        int nt = (r >> 5) & 7;          // 0..7  (n8 tile)
        int t  = r & 31;                // lane
        int k0 = ks * 16 + (t & 3) * 2;
        int n  = nt * 8 + (t >> 2);
        const int base = (n >> 3) * (F_IN * F_HID) + (n & 7);
        float w00 = W1[base + k0 * F_HID];
        float w01 = W1[base + (k0 + 1) * F_HID];
        float w08 = W1[base + (k0 + 8) * F_HID];
        float w09 = W1[base + (k0 + 9) * F_HID];
        uint2 v;
        if (term == 0) {
            v.x = (uint32_t)bf16_bits(w00) | ((uint32_t)bf16_bits(w01) << 16);
            v.y = (uint32_t)bf16_bits(w08) | ((uint32_t)bf16_bits(w09) << 16);
            g_Wfhi[(ks * 8 + nt) * 32 + t] = v;
        } else {
            __nv_bfloat16 b00 = __float2bfloat16_rn(w00), b01 = __float2bfloat16_rn(w01);
            __nv_bfloat16 b08 = __float2bfloat16_rn(w08), b09 = __float2bfloat16_rn(w09);
            unsigned short l00 = bf16_bits(w00 - __bfloat162float(b00));
            unsigned short l01 = bf16_bits(w01 - __bfloat162float(b01));
            unsigned short l08 = bf16_bits(w08 - __bfloat162float(b08));
            unsigned short l09 = bf16_bits(w09 - __bfloat162float(b09));
            v.x = (uint32_t)l00 | ((uint32_t)l01 << 16);
            v.y = (uint32_t)l08 | ((uint32_t)l09 << 16);
            g_Wflo[(ks * 8 + nt) * 32 + t] = v;
        }
    } else {
        int i = (bid - 64) * 256 + tid;   // < 1024 = (O1/2)*32
        int p = i >> 5, l = i & 31;
        int o0 = 2 * l, o1 = 2 * l + 1;
        int k0 = 2 * p, k1 = 2 * p + 1;
        ulonglong2 v;
        v.x = pack2(W2[k0 * NLAB + o0], W2[k1 * NLAB + o0]);
        v.y = pack2(W2[k0 * NLAB + o1], W2[k1 * NLAB + o1]);
        g_W2p[i] = v;
    }
}

// ================= KH: hist ×4 vectorized (rank-storing)  [chain A] =================
#define HIST4_BLKS ((EE + 1023) / 1024)
__global__ __launch_bounds__(256) void khist(const int* __restrict__ dst) {
    int e = (blockIdx.x * blockDim.x + threadIdx.x) * 4;
    if (e + 3 < EE) {
        int4 d4 = *(const int4*)&dst[e];
        int4 r4;
        r4.x = atomicAdd(&g_cnt[d4.x], 1);
        r4.y = atomicAdd(&g_cnt[d4.y], 1);
        r4.z = atomicAdd(&g_cnt[d4.z], 1);
        r4.w = atomicAdd(&g_cnt[d4.w], 1);
        *(int4*)&g_rank[e] = r4;
    } else {
        for (int q = e; q < EE; q++) g_rank[q] = atomicAdd(&g_cnt[dst[q]], 1);
    }
}

// ---- block-local inclusive scan helper (256 threads) ----
__device__ __forceinline__ int block_scan_incl_256(int v, int tid, int* wsum) {
    const int lane = tid & 31, wid = tid >> 5;
    int x = v;
#pragma unroll
    for (int d = 1; d < 32; d <<= 1) {
        int y = __shfl_up_sync(FULLM, x, d);
        if (lane >= d) x += y;
    }
    if (lane == 31) wsum[wid] = x;
    __syncthreads();
    if (wid == 0) {
        int s = (lane < 8) ? wsum[lane] : 0;
#pragma unroll
        for (int d = 1; d < 8; d <<= 1) {
            int y = __shfl_up_sync(FULLM, s, d);
            if (lane >= d) s += y;
        }
        if (lane < 8) wsum[lane] = s;
    }
    __syncthreads();
    return x + (wid ? wsum[wid - 1] : 0);
}

__global__ __launch_bounds__(256) void kscan_a() {
    __shared__ int wsum[8];
    const int b = blockIdx.x, t = threadIdx.x;
    const int i = b * 256 + t;
    int v = (i < NN) ? g_cnt[i] : 0;
    int incl = block_scan_incl_256(v, t, wsum);
    if (i < NN) g_off[i] = incl - v;
    if (t == 255) g_bsum[b] = incl;
}

__global__ __launch_bounds__(256) void kscan_b() {
    __shared__ int wsum[8];
    const int t = threadIdx.x;
    int v = (t < SCAN_BLKS) ? g_bsum[t] : 0;
    int incl = block_scan_incl_256(v, t, wsum);
    g_bscan[t] = incl - v;
    if (t == 255) g_off[NN] = incl;
}

__global__ __launch_bounds__(256) void kscan_c() {
    const int b = blockIdx.x, t = threadIdx.x;
    const int i = b * 256 + t;
    if (i < NN) g_off[i] += g_bscan[b];
}

// ===== K2: gemm1 via bf16 mma, DIRECT-LDG A-fragments (no smem, no syncs) [chain B] =====
// A fragments are thread-exclusive -> smem staging bought nothing. Each thread
// streams its own 4 float2 per k16-step from global (32B-sector coalesced),
// converts to bf16 hi/lo in regs, and feeds 24 MMAs. DRAM stays busy throughout.
#define G1M 128   // node rows per block
__global__ __launch_bounds__(256) void k2_gemm1(const float* __restrict__ x,
                                                const float* __restrict__ a1s,
                                                const float* __restrict__ a1d) {
    const int tid = threadIdx.x;
    const int lane = tid & 31;
    const int w = tid >> 5;
    const int nb0 = blockIdx.x * G1M;
    const int wr0 = w * 16 + (lane >> 2);
    const int kk0 = (lane & 3) * 2;
    const int g0 = nb0 + wr0;
    const int g1 = g0 + 8;
    const bool ok0 = g0 < NN, ok1 = g1 < NN;
    const float* row0 = x + (size_t)(ok0 ? g0 : 0) * F_IN + kk0;
    const float* row1 = x + (size_t)(ok1 ? g1 : 0) * F_IN + kk0;

    float acc[8][4];
#pragma unroll
    for (int nt = 0; nt < 8; nt++)
#pragma unroll
        for (int q = 0; q < 4; q++) acc[nt][q] = 0.f;

#pragma unroll 2
    for (int ks = 0; ks < 32; ks++) {
        const int kb = ks * 16;
        float2 v0 = *(const float2*)&row0[kb];
        float2 v1 = *(const float2*)&row1[kb];
        float2 v2 = *(const float2*)&row0[kb + 8];
        float2 v3 = *(const float2*)&row1[kb + 8];
        uint32_t ah0, al0, ah1, al1, ah2, al2, ah3, al3;
        cvt_hilo(v0, ah0, al0);
        cvt_hilo(v1, ah1, al1);
        cvt_hilo(v2, ah2, al2);
        cvt_hilo(v3, ah3, al3);
        const uint2* bhp = &g_Wfhi[ks * 8 * 32 + lane];
        const uint2* blp = &g_Wflo[ks * 8 * 32 + lane];
#pragma unroll
        for (int nt = 0; nt < 8; nt++) {
            uint2 bh = __ldg(&bhp[nt * 32]);
            uint2 bl = __ldg(&blp[nt * 32]);
            mma_bf16(acc[nt], ah0, ah1, ah2, ah3, bh.x, bh.y);
            mma_bf16(acc[nt], ah0, ah1, ah2, ah3, bl.x, bl.y);
            mma_bf16(acc[nt], al0, al1, al2, al3, bh.x, bh.y);
        }
    }

    // epilogue: store Wh1 + per-head es1/ed1 (head == nt)
    const float2* a1s2 = (const float2*)a1s;
    const float2* a1d2 = (const float2*)a1d;
#pragma unroll
    for (int nt = 0; nt < 8; nt++) {
        int col = nt * 8 + kk0;
        float2 as = __ldg(&a1s2[col >> 1]);
        float2 ad = __ldg(&a1d2[col >> 1]);
        float c0 = acc[nt][0], c1 = acc[nt][1], c2 = acc[nt][2], c3 = acc[nt][3];
        if (ok0) *(float2*)&g_Wh1[(size_t)g0 * O1 + col] = make_float2(c0, c1);
        if (ok1) *(float2*)&g_Wh1[(size_t)g1 * O1 + col] = make_float2(c2, c3);
        float ps0 = c0 * as.x + c1 * as.y;
        float pd0 = c0 * ad.x + c1 * ad.y;
        float ps1 = c2 * as.x + c3 * as.y;
        float pd1 = c2 * ad.x + c3 * ad.y;
        ps0 += __shfl_xor_sync(FULLM, ps0, 1); ps0 += __shfl_xor_sync(FULLM, ps0, 2);
        pd0 += __shfl_xor_sync(FULLM, pd0, 1); pd0 += __shfl_xor_sync(FULLM, pd0, 2);
        ps1 += __shfl_xor_sync(FULLM, ps1, 1); ps1 += __shfl_xor_sync(FULLM, ps1, 2);
        pd1 += __shfl_xor_sync(FULLM, pd1, 1); pd1 += __shfl_xor_sync(FULLM, pd1, 2);
        if ((lane & 3) == 0) {
            if (ok0) { g_es1[g0 * H1 + nt] = ps0; g_ed1[g0 * H1 + nt] = pd0; }
            if (ok1) { g_es1[g1 * H1 + nt] = ps1; g_ed1[g1 * H1 + nt] = pd1; }
        }
    }
}

// ============ K3: pure scatter (atomic-free, rank-based), ×4  [chain A] ============
__global__ void k3_scatter(const int* __restrict__ src, const int* __restrict__ dst) {
    int e = (blockIdx.x * blockDim.x + threadIdx.x) * 4;
    if (e + 3 < EE) {
        int4 d4 = *(const int4*)&dst[e];
        int4 s4 = *(const int4*)&src[e];
        int4 r4 = *(const int4*)&g_rank[e];
        g_ssrc[g_off[d4.x] + r4.x] = s4.x;
        g_ssrc[g_off[d4.y] + r4.y] = s4.y;
        g_ssrc[g_off[d4.z] + r4.z] = s4.z;
        g_ssrc[g_off[d4.w] + r4.w] = s4.w;
    } else {
        for (int q = e; q < EE; q++) g_ssrc[g_off[dst[q]] + g_rank[q]] = src[q];
    }
}

// ====== K4: layer-1 aggregate, batch-8, inline p (pipelined es1 gather) + ELU ======
__global__ __launch_bounds__(256) void k4_agg1() {
    int node = (blockIdx.x * blockDim.x + threadIdx.x) >> 5;
    int lane = threadIdx.x & 31;
    if (node >= NN) return;
    const int beg = g_off[node], end = g_off[node + 1];
    const int srcg = lane & 0x1C;
    const int e4 = lane & 3;
    const int e8 = lane & 7;
    const int h = lane >> 2;
    const float edh = g_ed1[node * H1 + h];

    int   s_l = g_ssrc[beg + e8];
    int   sA  = __shfl_sync(FULLM, s_l, e4);
    int   sB  = __shfl_sync(FULLM, s_l, 4 + e4);
    float esA = g_es1[sA * H1 + h];
    float esB = g_es1[sB * H1 + h];

    float sumP = 0.f;
    unsigned long long acc0 = 0ull, acc1 = 0ull;
    for (int base = beg; base < end; base += 8) {
        int   s_n  = g_ssrc[base + 8 + e8];
        int   sAn  = __shfl_sync(FULLM, s_n, e4);
        int   sBn  = __shfl_sync(FULLM, s_n, 4 + e4);
        float esAn = g_es1[sAn * H1 + h];
        float esBn = g_es1[sBn * H1 + h];

        const int m = end - base;
        float pA = (e4 < m)     ? __expf(lrelu_f(esA + edh)) : 0.f;
        float pB = (4 + e4 < m) ? __expf(lrelu_f(esB + edh)) : 0.f;
        sumP += pA + pB;
#pragma unroll
        for (int j = 0; j < 8; j++) {
            int s   = __shfl_sync(FULLM, s_l, j);
            float p = __shfl_sync(FULLM, (j < 4) ? pA : pB, srcg | (j & 3));
            unsigned long long w2 = *(const unsigned long long*)
                &g_Wh1[s * O1 + 2 * lane];
            if (j & 1) fma2(acc1, pack2(p, p), w2);
            else       fma2(acc0, pack2(p, p), w2);
        }
        s_l = s_n; esA = esAn; esB = esBn;
    }
    sumP += __shfl_xor_sync(FULLM, sumP, 1);
    sumP += __shfl_xor_sync(FULLM, sumP, 2);

    const float inv = 1.f / (sumP + 1e-10f);
    float2 a0 = unpack2(acc0);
    float2 a1 = unpack2(acc1);
    *(float2*)&g_h1[node * O1 + 2 * lane] =
        make_float2(elu_f((a0.x + a1.x) * inv), elu_f((a0.y + a1.y) * inv));
}

// ========= K4c: GEMM2 (batched, W2 packed, f32x2) + es2/ed2 epilogue =========
#define G2_NB 64
__global__ __launch_bounds__(256) void k4c_gemm2(const float* __restrict__ a2s,
                                                 const float* __restrict__ a2d) {
    __shared__ float hs[G2_NB][O1];   // 16KB
    const int tid = threadIdx.x;
    const int lane = tid & 31;
    const int w = tid >> 5;
    const int nb0 = blockIdx.x * G2_NB;

    for (int idx = tid; idx < G2_NB * (O1 / 4); idx += 256) {
        int n = idx >> 4;
        int c = idx & 15;
        int g = nb0 + n;
        float4 v = make_float4(0.f, 0.f, 0.f, 0.f);
        if (g < NN) v = *(const float4*)&g_h1[(size_t)g * O1 + c * 4];
        *(float4*)&hs[n][c * 4] = v;
    }
    __syncthreads();

    unsigned long long acc[8][2];
#pragma unroll
    for (int n = 0; n < 8; n++) { acc[n][0] = 0ull; acc[n][1] = 0ull; }

    const int nrow = w * 8;
#pragma unroll 4
    for (int q = 0; q < O1 / 2; q += 2) {
        ulonglong2 wA = g_W2p[q * 32 + lane];
        ulonglong2 wB = g_W2p[(q + 1) * 32 + lane];
#pragma unroll
        for (int n = 0; n < 8; n++) {
            ulonglong2 xv = *(const ulonglong2*)&hs[nrow + n][2 * q];
            fma2(acc[n][0], xv.x, wA.x);
            fma2(acc[n][1], xv.x, wA.y);
            fma2(acc[n][0], xv.y, wB.x);
            fma2(acc[n][1], xv.y, wB.y);
        }
    }

    const float as0 = a2s[2 * lane], as1 = a2s[2 * lane + 1];
    const float ad0 = a2d[2 * lane], ad1 = a2d[2 * lane + 1];
#pragma unroll
    for (int n = 0; n < 8; n++) {
        int g = nb0 + w * 8 + n;
        if (g >= NN) continue;
        float2 p0 = unpack2(acc[n][0]);
        float2 p1 = unpack2(acc[n][1]);
        float o0 = p0.x + p0.y;
        float o1 = p1.x + p1.y;
        *(float2*)&g_Wh2[g * NLAB + 2 * lane] = make_float2(o0, o1);
        float ps = o0 * as0 + o1 * as1;
        float pd = o0 * ad0 + o1 * ad1;
#pragma unroll
        for (int o = 16; o; o >>= 1) {
            ps += __shfl_xor_sync(FULLM, ps, o);
            pd += __shfl_xor_sync(FULLM, pd, o);
        }
        if (lane == 0) { g_es2[g] = ps; g_ed2[g] = pd; }
    }
}

// ====== K5: layer-2 aggregate, batch-32 per-lane staging + gated 8-sub-batches ======
__global__ __launch_bounds__(256) void k5_agg2(float* __restrict__ out) {
    int gid = blockIdx.x * blockDim.x + threadIdx.x;
    if (gid < NN) g_cnt[gid] = 0;   // leave cnt zeroed for the next call

    int node = gid >> 5;
    int lane = threadIdx.x & 31;
    if (node >= NN) return;
    const int beg = g_off[node], end = g_off[node + 1];
    const float ed = g_ed2[node];

    float sumP = 0.f;
    unsigned long long acc0 = 0ull, acc1 = 0ull;

    for (int base = beg; base < end; base += 32) {
        const int m = end - base;
        int   s_l = g_ssrc[base + lane];           // pad zero-init -> safe
        float v_l = g_es2[s_l];
        float p_l = (lane < m) ? __expf(lrelu_f(v_l + ed)) : 0.f;
        sumP += p_l;
#pragma unroll
        for (int sb = 0; sb < 4; sb++) {
            if (sb * 8 >= m) break;
#pragma unroll
            for (int j = 0; j < 8; j++) {
                const int jj = sb * 8 + j;
                int s   = __shfl_sync(FULLM, s_l, jj);
                float p = __shfl_sync(FULLM, p_l, jj);
                unsigned long long w2 = *(const unsigned long long*)
                    &g_Wh2[s * NLAB + 2 * lane];
                if (j & 1) fma2(acc1, pack2(p, p), w2);
                else       fma2(acc0, pack2(p, p), w2);
            }
        }
    }
#pragma unroll
    for (int o = 16; o; o >>= 1) sumP += __shfl_xor_sync(FULLM, sumP, o);

    const float inv = 1.f / (sumP + 1e-10f);
    float2 a0 = unpack2(acc0);
    float2 a1 = unpack2(acc1);
    float o0 = (a0.x + a1.x) * inv;
    float o1 = (a0.y + a1.y) * inv;

    float m2 = fmaxf(o0, o1);
#pragma unroll
    for (int o = 16; o; o >>= 1) m2 = fmaxf(m2, __shfl_xor_sync(FULLM, m2, o));
    float e0 = __expf(o0 - m2);
    float e1 = __expf(o1 - m2);
    float s2 = e0 + e1;
#pragma unroll
    for (int o = 16; o; o >>= 1) s2 += __shfl_xor_sync(FULLM, s2, o);
    float r = 1.f / s2;
    *(float2*)&out[(size_t)node * NLAB + 2 * lane] = make_float2(e0 * r, e1 * r);
}

// ---------------- launch: fork/join — chain A (edge prep) ∥ chain B (dense) ----------------
extern "C" void kernel_launch(void* const* d_in, const int* in_sizes, int n_in,
                              void* d_out, int out_size) {
    const float* x    = (const float*)d_in[0];
    const float* W1   = (const float*)d_in[1];
    const float* a1s  = (const float*)d_in[2];
    const float* a1d  = (const float*)d_in[3];
    const float* W2   = (const float*)d_in[4];
    const float* a2s  = (const float*)d_in[5];
    const float* a2d  = (const float*)d_in[6];
    const int*   src  = (const int*)d_in[7];
    const int*   dst  = (const int*)d_in[8];
    float* out = (float*)d_out;

    static cudaStream_t sB = nullptr;
    static cudaEvent_t evFork = nullptr, evJoin = nullptr;
    if (sB == nullptr) {
        cudaStreamCreateWithFlags(&sB, cudaStreamNonBlocking);
        cudaEventCreateWithFlags(&evFork, cudaEventDisableTiming);
        cudaEventCreateWithFlags(&evJoin, cudaEventDisableTiming);
    }

    cudaEventRecord(evFork, 0);
    cudaStreamWaitEvent(sB, evFork, 0);

    // submission order keeps k2_gemm1 4th (ncu profiles the 4th launch);
    // execution order is unchanged (streams carry the real dependencies).
    kpack<<<68, 256, 0, sB>>>(W1, W2);              // 1 (chain B)
    khist<<<HIST4_BLKS, 256>>>(dst);                // 2 (chain A)
    kscan_a<<<SCAN_BLKS, 256>>>();                  // 3 (chain A)
    k2_gemm1<<<(NN + G1M - 1) / G1M, 256, 0, sB>>>(x, a1s, a1d);  // 4 (chain B)
    kscan_b<<<1, 256>>>();                          // 5 (chain A)
    kscan_c<<<SCAN_BLKS, 256>>>();                  // 6 (chain A)
    k3_scatter<<<HIST4_BLKS, 256>>>(src, dst);      // 7 (chain A)

    // join
    cudaEventRecord(evJoin, sB);
    cudaStreamWaitEvent(0, evJoin, 0);

    // serial tail
    k4_agg1<<<(NN * 32 + 255) / 256, 256>>>();
    k4c_gemm2<<<(NN + G2_NB - 1) / G2_NB, 256>>>(a2s, a2d);
    k5_agg2<<<(NN * 32 + 255) / 256, 256>>>(out);
}

// round 17
// speedup vs baseline: 1.7511x; 1.0401x over previous
#include <cuda_runtime.h>
#include <cuda_bf16.h>
#include <math.h>
#include <stdint.h>

// ---------------- problem constants ----------------
#define NN 50000
#define EE 800000
#define F_IN 512
#define H1 8
#define F_HID 8
#define O1 64          // H1*F_HID
#define NLAB 64
#define LRELU 0.2f

#define FULLM 0xffffffffu
#define SCAN_BLKS ((NN + 255) / 256)   // 196

// ---------------- device scratch (no allocs allowed) ----------------
__device__ uint2 g_Wfhi[32 * 8 * 32];          // W1 hi bf16, mma B-fragment layout
__device__ uint2 g_Wflo[32 * 8 * 32];          // W1 lo bf16 (residual)
__device__ ulonglong2 g_W2p[(O1 / 2) * 32];    // W2 packed f32x2 (gemm2)
__device__ float g_Wh1[(size_t)NN * O1];       // layer-1 node features
__device__ float g_es1[NN * H1];
__device__ float g_ed1[NN * H1];
__device__ float g_h1[(size_t)NN * O1];        // post-aggregation, post-ELU
__device__ float g_Wh2[(size_t)NN * NLAB];
__device__ float g_es2[NN];
__device__ float g_ed2[NN];
__device__ int   g_cnt[NN];                    // zero at entry (re-zeroed at tail of k5)
__device__ int   g_rank[EE];
__device__ int   g_off[NN + 1];
__device__ int   g_bsum[256];
__device__ int   g_bscan[256];
__device__ int   g_ssrc[EE + 64];              // +pad (zero-init) for unguarded batch loads

// ---------------- helpers ----------------
__device__ __forceinline__ unsigned long long pack2(float lo, float hi) {
    unsigned long long r;
    asm("mov.b64 %0, {%1, %2};" : "=l"(r) : "f"(lo), "f"(hi));
    return r;
}
__device__ __forceinline__ void fma2(unsigned long long& acc, unsigned long long a,
                                     unsigned long long b) {
    asm("fma.rn.f32x2 %0, %1, %2, %0;" : "+l"(acc) : "l"(a), "l"(b));
}
__device__ __forceinline__ float2 unpack2(unsigned long long v) {
    float lo, hi;
    asm("mov.b64 {%0, %1}, %2;" : "=f"(lo), "=f"(hi) : "l"(v));
    return make_float2(lo, hi);
}
__device__ __forceinline__ float lrelu_f(float v) { return fmaxf(v, LRELU * v); }
__device__ __forceinline__ float elu_f(float v)   { return v > 0.f ? v : __expf(v) - 1.f; }

__device__ __forceinline__ void mma_bf16(float* c, uint32_t a0, uint32_t a1,
                                         uint32_t a2, uint32_t a3,
                                         uint32_t b0, uint32_t b1) {
    asm volatile(
        "mma.sync.aligned.m16n8k16.row.col.f32.bf16.bf16.f32 "
        "{%0,%1,%2,%3}, {%4,%5,%6,%7}, {%8,%9}, {%0,%1,%2,%3};"
        : "+f"(c[0]), "+f"(c[1]), "+f"(c[2]), "+f"(c[3])
        : "r"(a0), "r"(a1), "r"(a2), "r"(a3), "r"(b0), "r"(b1));
}
__device__ __forceinline__ unsigned short bf16_bits(float v) {
    __nv_bfloat16 b = __float2bfloat16_rn(v);
    return *reinterpret_cast<unsigned short*>(&b);
}
// fp32 pair -> bf16x2 hi + bf16x2 lo (residual)
__device__ __forceinline__ void cvt_hilo(float2 v, uint32_t& hi, uint32_t& lo) {
    __nv_bfloat162 h = __float22bfloat162_rn(v);
    float2 f = __bfloat1622float2(h);
    __nv_bfloat162 l = __float22bfloat162_rn(make_float2(v.x - f.x, v.y - f.y));
    hi = *reinterpret_cast<uint32_t*>(&h);
    lo = *reinterpret_cast<uint32_t*>(&l);
}

// ===== KP: pack W1 into bf16 hi/lo B-fragments (64 blk) + pack W2 (4 blk) [chain B] =====
__global__ __launch_bounds__(256) void kpack(const float* __restrict__ W1,
                                             const float* __restrict__ W2) {
    const int bid = blockIdx.x;
    const int tid = threadIdx.x;
    if (bid < 64) {
        int i = bid * 256 + tid;        // 0..16383
        int term = i >> 13;             // 0 = hi, 1 = lo
        int r = i & 8191;
        int ks = r >> 8;                // 0..31 (k16 step)
        int nt = (r >> 5) & 7;          // 0..7  (n8 tile)
        int t  = r & 31;                // lane
        int k0 = ks * 16 + (t & 3) * 2;
        int n  = nt * 8 + (t >> 2);
        const int base = (n >> 3) * (F_IN * F_HID) + (n & 7);
        float w00 = W1[base + k0 * F_HID];
        float w01 = W1[base + (k0 + 1) * F_HID];
        float w08 = W1[base + (k0 + 8) * F_HID];
        float w09 = W1[base + (k0 + 9) * F_HID];
        uint2 v;
        if (term == 0) {
            v.x = (uint32_t)bf16_bits(w00) | ((uint32_t)bf16_bits(w01) << 16);
            v.y = (uint32_t)bf16_bits(w08) | ((uint32_t)bf16_bits(w09) << 16);
            g_Wfhi[(ks * 8 + nt) * 32 + t] = v;
        } else {
            __nv_bfloat16 b00 = __float2bfloat16_rn(w00), b01 = __float2bfloat16_rn(w01);
            __nv_bfloat16 b08 = __float2bfloat16_rn(w08), b09 = __float2bfloat16_rn(w09);
            unsigned short l00 = bf16_bits(w00 - __bfloat162float(b00));
            unsigned short l01 = bf16_bits(w01 - __bfloat162float(b01));
            unsigned short l08 = bf16_bits(w08 - __bfloat162float(b08));
            unsigned short l09 = bf16_bits(w09 - __bfloat162float(b09));
            v.x = (uint32_t)l00 | ((uint32_t)l01 << 16);
            v.y = (uint32_t)l08 | ((uint32_t)l09 << 16);
            g_Wflo[(ks * 8 + nt) * 32 + t] = v;
        }
    } else {
        int i = (bid - 64) * 256 + tid;   // < 1024 = (O1/2)*32
        int p = i >> 5, l = i & 31;
        int o0 = 2 * l, o1 = 2 * l + 1;
        int k0 = 2 * p, k1 = 2 * p + 1;
        ulonglong2 v;
        v.x = pack2(W2[k0 * NLAB + o0], W2[k1 * NLAB + o0]);
        v.y = pack2(W2[k0 * NLAB + o1], W2[k1 * NLAB + o1]);
        g_W2p[i] = v;
    }
}

// ================= KH: hist ×4 vectorized (rank-storing)  [chain A] =================
#define HIST4_BLKS ((EE + 1023) / 1024)
__global__ __launch_bounds__(256) void khist(const int* __restrict__ dst) {
    int e = (blockIdx.x * blockDim.x + threadIdx.x) * 4;
    if (e + 3 < EE) {
        int4 d4 = *(const int4*)&dst[e];
        int4 r4;
        r4.x = atomicAdd(&g_cnt[d4.x], 1);
        r4.y = atomicAdd(&g_cnt[d4.y], 1);
        r4.z = atomicAdd(&g_cnt[d4.z], 1);
        r4.w = atomicAdd(&g_cnt[d4.w], 1);
        *(int4*)&g_rank[e] = r4;
    } else {
        for (int q = e; q < EE; q++) g_rank[q] = atomicAdd(&g_cnt[dst[q]], 1);
    }
}

// ---- block-local inclusive scan helper (256 threads) ----
__device__ __forceinline__ int block_scan_incl_256(int v, int tid, int* wsum) {
    const int lane = tid & 31, wid = tid >> 5;
    int x = v;
#pragma unroll
    for (int d = 1; d < 32; d <<= 1) {
        int y = __shfl_up_sync(FULLM, x, d);
        if (lane >= d) x += y;
    }
    if (lane == 31) wsum[wid] = x;
    __syncthreads();
    if (wid == 0) {
        int s = (lane < 8) ? wsum[lane] : 0;
#pragma unroll
        for (int d = 1; d < 8; d <<= 1) {
            int y = __shfl_up_sync(FULLM, s, d);
            if (lane >= d) s += y;
        }
        if (lane < 8) wsum[lane] = s;
    }
    __syncthreads();
    return x + (wid ? wsum[wid - 1] : 0);
}

__global__ __launch_bounds__(256) void kscan_a() {
    __shared__ int wsum[8];
    const int b = blockIdx.x, t = threadIdx.x;
    const int i = b * 256 + t;
    int v = (i < NN) ? g_cnt[i] : 0;
    int incl = block_scan_incl_256(v, t, wsum);
    if (i < NN) g_off[i] = incl - v;
    if (t == 255) g_bsum[b] = incl;
}

__global__ __launch_bounds__(256) void kscan_b() {
    __shared__ int wsum[8];
    const int t = threadIdx.x;
    int v = (t < SCAN_BLKS) ? g_bsum[t] : 0;
    int incl = block_scan_incl_256(v, t, wsum);
    g_bscan[t] = incl - v;
    if (t == 255) g_off[NN] = incl;
}

__global__ __launch_bounds__(256) void kscan_c() {
    const int b = blockIdx.x, t = threadIdx.x;
    const int i = b * 256 + t;
    if (i < NN) g_off[i] += g_bscan[b];
}

// ===== K2: gemm1 bf16 mma, 2-way K-SPLIT (2 warps/tile) + sw-pipelined x loads =====
// 8 warps: wt = warp&3 selects a 16-row tile, kh = warp>>2 selects K half.
// Doubles resident warps (6250 total), halves each warp's serial DRAM chain.
// Partials combined via conflict-free smem; k-lo warps run the epilogue.
#define G1M 64   // node rows per block (4 tiles x 16)
__global__ __launch_bounds__(256) void k2_gemm1(const float* __restrict__ x,
                                                const float* __restrict__ a1s,
                                                const float* __restrict__ a1d) {
    __shared__ float sacc[4][32][32];   // [tile][frag idx][lane] 16KB
    const int tid = threadIdx.x;
    const int lane = tid & 31;
    const int w = tid >> 5;
    const int wt = w & 3;
    const int kh = w >> 2;
    const int nb0 = blockIdx.x * G1M;
    const int wr0 = wt * 16 + (lane >> 2);
    const int kk0 = (lane & 3) * 2;
    const int g0 = nb0 + wr0;
    const int g1 = g0 + 8;
    const bool ok0 = g0 < NN, ok1 = g1 < NN;
    const float* row0 = x + (size_t)(ok0 ? g0 : 0) * F_IN + kk0;
    const float* row1 = x + (size_t)(ok1 ? g1 : 0) * F_IN + kk0;

    float acc[8][4];
#pragma unroll
    for (int nt = 0; nt < 8; nt++)
#pragma unroll
        for (int q = 0; q < 4; q++) acc[nt][q] = 0.f;

    const int ksbeg = kh * 16, ksend = ksbeg + 16;
    // prefetch first iteration's x fragment
    int kb = ksbeg * 16;
    float2 v0 = *(const float2*)&row0[kb];
    float2 v1 = *(const float2*)&row1[kb];
    float2 v2 = *(const float2*)&row0[kb + 8];
    float2 v3 = *(const float2*)&row1[kb + 8];

#pragma unroll 2
    for (int ks = ksbeg; ks < ksend; ks++) {
        // prefetch next (wraps to ksbeg on last trip: in-bounds dummy)
        const int kbn = (ks + 1 < ksend) ? (ks + 1) * 16 : ksbeg * 16;
        float2 n0 = *(const float2*)&row0[kbn];
        float2 n1 = *(const float2*)&row1[kbn];
        float2 n2 = *(const float2*)&row0[kbn + 8];
        float2 n3 = *(const float2*)&row1[kbn + 8];

        uint32_t ah0, al0, ah1, al1, ah2, al2, ah3, al3;
        cvt_hilo(v0, ah0, al0);
        cvt_hilo(v1, ah1, al1);
        cvt_hilo(v2, ah2, al2);
        cvt_hilo(v3, ah3, al3);
        const uint2* bhp = &g_Wfhi[ks * 8 * 32 + lane];
        const uint2* blp = &g_Wflo[ks * 8 * 32 + lane];
#pragma unroll
        for (int nt = 0; nt < 8; nt++) {
            uint2 bh = __ldg(&bhp[nt * 32]);
            uint2 bl = __ldg(&blp[nt * 32]);
            mma_bf16(acc[nt], ah0, ah1, ah2, ah3, bh.x, bh.y);
            mma_bf16(acc[nt], ah0, ah1, ah2, ah3, bl.x, bl.y);
            mma_bf16(acc[nt], al0, al1, al2, al3, bh.x, bh.y);
        }
        v0 = n0; v1 = n1; v2 = n2; v3 = n3;
    }

    // combine k halves: hi warps deposit, lo warps add + epilogue
    if (kh == 1) {
#pragma unroll
        for (int nt = 0; nt < 8; nt++)
#pragma unroll
            for (int q = 0; q < 4; q++)
                sacc[wt][nt * 4 + q][lane] = acc[nt][q];
    }
    __syncthreads();
    if (kh == 1) return;
#pragma unroll
    for (int nt = 0; nt < 8; nt++)
#pragma unroll
        for (int q = 0; q < 4; q++)
            acc[nt][q] += sacc[wt][nt * 4 + q][lane];

    // epilogue: store Wh1 + per-head es1/ed1 (head == nt)
    const float2* a1s2 = (const float2*)a1s;
    const float2* a1d2 = (const float2*)a1d;
#pragma unroll
    for (int nt = 0; nt < 8; nt++) {
        int col = nt * 8 + kk0;
        float2 as = __ldg(&a1s2[col >> 1]);
        float2 ad = __ldg(&a1d2[col >> 1]);
        float c0 = acc[nt][0], c1 = acc[nt][1], c2 = acc[nt][2], c3 = acc[nt][3];
        if (ok0) *(float2*)&g_Wh1[(size_t)g0 * O1 + col] = make_float2(c0, c1);
        if (ok1) *(float2*)&g_Wh1[(size_t)g1 * O1 + col] = make_float2(c2, c3);
        float ps0 = c0 * as.x + c1 * as.y;
        float pd0 = c0 * ad.x + c1 * ad.y;
        float ps1 = c2 * as.x + c3 * as.y;
        float pd1 = c2 * ad.x + c3 * ad.y;
        ps0 += __shfl_xor_sync(FULLM, ps0, 1); ps0 += __shfl_xor_sync(FULLM, ps0, 2);
        pd0 += __shfl_xor_sync(FULLM, pd0, 1); pd0 += __shfl_xor_sync(FULLM, pd0, 2);
        ps1 += __shfl_xor_sync(FULLM, ps1, 1); ps1 += __shfl_xor_sync(FULLM, ps1, 2);
        pd1 += __shfl_xor_sync(FULLM, pd1, 1); pd1 += __shfl_xor_sync(FULLM, pd1, 2);
        if ((lane & 3) == 0) {
            if (ok0) { g_es1[g0 * H1 + nt] = ps0; g_ed1[g0 * H1 + nt] = pd0; }
            if (ok1) { g_es1[g1 * H1 + nt] = ps1; g_ed1[g1 * H1 + nt] = pd1; }
        }
    }
}

// ============ K3: pure scatter (atomic-free, rank-based), ×4  [chain A] ============
__global__ void k3_scatter(const int* __restrict__ src, const int* __restrict__ dst) {
    int e = (blockIdx.x * blockDim.x + threadIdx.x) * 4;
    if (e + 3 < EE) {
        int4 d4 = *(const int4*)&dst[e];
        int4 s4 = *(const int4*)&src[e];
        int4 r4 = *(const int4*)&g_rank[e];
        g_ssrc[g_off[d4.x] + r4.x] = s4.x;
        g_ssrc[g_off[d4.y] + r4.y] = s4.y;
        g_ssrc[g_off[d4.z] + r4.z] = s4.z;
        g_ssrc[g_off[d4.w] + r4.w] = s4.w;
    } else {
        for (int q = e; q < EE; q++) g_ssrc[g_off[dst[q]] + g_rank[q]] = src[q];
    }
}

// ====== K4: layer-1 aggregate, batch-8, inline p (pipelined es1 gather) + ELU ======
__global__ __launch_bounds__(256) void k4_agg1() {
    int node = (blockIdx.x * blockDim.x + threadIdx.x) >> 5;
    int lane = threadIdx.x & 31;
    if (node >= NN) return;
    const int beg = g_off[node], end = g_off[node + 1];
    const int srcg = lane & 0x1C;
    const int e4 = lane & 3;
    const int e8 = lane & 7;
    const int h = lane >> 2;
    const float edh = g_ed1[node * H1 + h];

    int   s_l = g_ssrc[beg + e8];
    int   sA  = __shfl_sync(FULLM, s_l, e4);
    int   sB  = __shfl_sync(FULLM, s_l, 4 + e4);
    float esA = g_es1[sA * H1 + h];
    float esB = g_es1[sB * H1 + h];

    float sumP = 0.f;
    unsigned long long acc0 = 0ull, acc1 = 0ull;
    for (int base = beg; base < end; base += 8) {
        int   s_n  = g_ssrc[base + 8 + e8];
        int   sAn  = __shfl_sync(FULLM, s_n, e4);
        int   sBn  = __shfl_sync(FULLM, s_n, 4 + e4);
        float esAn = g_es1[sAn * H1 + h];
        float esBn = g_es1[sBn * H1 + h];

        const int m = end - base;
        float pA = (e4 < m)     ? __expf(lrelu_f(esA + edh)) : 0.f;
        float pB = (4 + e4 < m) ? __expf(lrelu_f(esB + edh)) : 0.f;
        sumP += pA + pB;
#pragma unroll
        for (int j = 0; j < 8; j++) {
            int s   = __shfl_sync(FULLM, s_l, j);
            float p = __shfl_sync(FULLM, (j < 4) ? pA : pB, srcg | (j & 3));
            unsigned long long w2 = *(const unsigned long long*)
                &g_Wh1[s * O1 + 2 * lane];
            if (j & 1) fma2(acc1, pack2(p, p), w2);
            else       fma2(acc0, pack2(p, p), w2);
        }
        s_l = s_n; esA = esAn; esB = esBn;
    }
    sumP += __shfl_xor_sync(FULLM, sumP, 1);
    sumP += __shfl_xor_sync(FULLM, sumP, 2);

    const float inv = 1.f / (sumP + 1e-10f);
    float2 a0 = unpack2(acc0);
    float2 a1 = unpack2(acc1);
    *(float2*)&g_h1[node * O1 + 2 * lane] =
        make_float2(elu_f((a0.x + a1.x) * inv), elu_f((a0.y + a1.y) * inv));
}

// ========= K4c: GEMM2 (batched, W2 packed, f32x2) + es2/ed2 epilogue =========
#define G2_NB 64
__global__ __launch_bounds__(256) void k4c_gemm2(const float* __restrict__ a2s,
                                                 const float* __restrict__ a2d) {
    __shared__ float hs[G2_NB][O1];   // 16KB
    const int tid = threadIdx.x;
    const int lane = tid & 31;
    const int w = tid >> 5;
    const int nb0 = blockIdx.x * G2_NB;

    for (int idx = tid; idx < G2_NB * (O1 / 4); idx += 256) {
        int n = idx >> 4;
        int c = idx & 15;
        int g = nb0 + n;
        float4 v = make_float4(0.f, 0.f, 0.f, 0.f);
        if (g < NN) v = *(const float4*)&g_h1[(size_t)g * O1 + c * 4];
        *(float4*)&hs[n][c * 4] = v;
    }
    __syncthreads();

    unsigned long long acc[8][2];
#pragma unroll
    for (int n = 0; n < 8; n++) { acc[n][0] = 0ull; acc[n][1] = 0ull; }

    const int nrow = w * 8;
#pragma unroll 4
    for (int q = 0; q < O1 / 2; q += 2) {
        ulonglong2 wA = g_W2p[q * 32 + lane];
        ulonglong2 wB = g_W2p[(q + 1) * 32 + lane];
#pragma unroll
        for (int n = 0; n < 8; n++) {
            ulonglong2 xv = *(const ulonglong2*)&hs[nrow + n][2 * q];
            fma2(acc[n][0], xv.x, wA.x);
            fma2(acc[n][1], xv.x, wA.y);
            fma2(acc[n][0], xv.y, wB.x);
            fma2(acc[n][1], xv.y, wB.y);
        }
    }

    const float as0 = a2s[2 * lane], as1 = a2s[2 * lane + 1];
    const float ad0 = a2d[2 * lane], ad1 = a2d[2 * lane + 1];
#pragma unroll
    for (int n = 0; n < 8; n++) {
        int g = nb0 + w * 8 + n;
        if (g >= NN) continue;
        float2 p0 = unpack2(acc[n][0]);
        float2 p1 = unpack2(acc[n][1]);
        float o0 = p0.x + p0.y;
        float o1 = p1.x + p1.y;
        *(float2*)&g_Wh2[g * NLAB + 2 * lane] = make_float2(o0, o1);
        float ps = o0 * as0 + o1 * as1;
        float pd = o0 * ad0 + o1 * ad1;
#pragma unroll
        for (int o = 16; o; o >>= 1) {
            ps += __shfl_xor_sync(FULLM, ps, o);
            pd += __shfl_xor_sync(FULLM, pd, o);
        }
        if (lane == 0) { g_es2[g] = ps; g_ed2[g] = pd; }
    }
}

// ====== K5: layer-2 aggregate, batch-32 per-lane staging + gated 8-sub-batches ======
__global__ __launch_bounds__(256) void k5_agg2(float* __restrict__ out) {
    int gid = blockIdx.x * blockDim.x + threadIdx.x;
    if (gid < NN) g_cnt[gid] = 0;   // leave cnt zeroed for the next call

    int node = gid >> 5;
    int lane = threadIdx.x & 31;
    if (node >= NN) return;
    const int beg = g_off[node], end = g_off[node + 1];
    const float ed = g_ed2[node];

    float sumP = 0.f;
    unsigned long long acc0 = 0ull, acc1 = 0ull;

    for (int base = beg; base < end; base += 32) {
        const int m = end - base;
        int   s_l = g_ssrc[base + lane];           // pad zero-init -> safe
        float v_l = g_es2[s_l];
        float p_l = (lane < m) ? __expf(lrelu_f(v_l + ed)) : 0.f;
        sumP += p_l;
#pragma unroll
        for (int sb = 0; sb < 4; sb++) {
            if (sb * 8 >= m) break;
#pragma unroll
            for (int j = 0; j < 8; j++) {
                const int jj = sb * 8 + j;
                int s   = __shfl_sync(FULLM, s_l, jj);
                float p = __shfl_sync(FULLM, p_l, jj);
                unsigned long long w2 = *(const unsigned long long*)
                    &g_Wh2[s * NLAB + 2 * lane];
                if (j & 1) fma2(acc1, pack2(p, p), w2);
                else       fma2(acc0, pack2(p, p), w2);
            }
        }
    }
#pragma unroll
    for (int o = 16; o; o >>= 1) sumP += __shfl_xor_sync(FULLM, sumP, o);

    const float inv = 1.f / (sumP + 1e-10f);
    float2 a0 = unpack2(acc0);
    float2 a1 = unpack2(acc1);
    float o0 = (a0.x + a1.x) * inv;
    float o1 = (a0.y + a1.y) * inv;

    float m2 = fmaxf(o0, o1);
#pragma unroll
    for (int o = 16; o; o >>= 1) m2 = fmaxf(m2, __shfl_xor_sync(FULLM, m2, o));
    float e0 = __expf(o0 - m2);
    float e1 = __expf(o1 - m2);
    float s2 = e0 + e1;
#pragma unroll
    for (int o = 16; o; o >>= 1) s2 += __shfl_xor_sync(FULLM, s2, o);
    float r = 1.f / s2;
    *(float2*)&out[(size_t)node * NLAB + 2 * lane] = make_float2(e0 * r, e1 * r);
}

// ---------------- launch: fork/join — chain A (edge prep) ∥ chain B (dense) ----------------
extern "C" void kernel_launch(void* const* d_in, const int* in_sizes, int n_in,
                              void* d_out, int out_size) {
    const float* x    = (const float*)d_in[0];
    const float* W1   = (const float*)d_in[1];
    const float* a1s  = (const float*)d_in[2];
    const float* a1d  = (const float*)d_in[3];
    const float* W2   = (const float*)d_in[4];
    const float* a2s  = (const float*)d_in[5];
    const float* a2d  = (const float*)d_in[6];
    const int*   src  = (const int*)d_in[7];
    const int*   dst  = (const int*)d_in[8];
    float* out = (float*)d_out;

    static cudaStream_t sB = nullptr;
    static cudaEvent_t evFork = nullptr, evJoin = nullptr;
    if (sB == nullptr) {
        cudaStreamCreateWithFlags(&sB, cudaStreamNonBlocking);
        cudaEventCreateWithFlags(&evFork, cudaEventDisableTiming);
        cudaEventCreateWithFlags(&evJoin, cudaEventDisableTiming);
    }

    cudaEventRecord(evFork, 0);
    cudaStreamWaitEvent(sB, evFork, 0);

    // submission order keeps k2_gemm1 4th (ncu profiles the 4th launch);
    // execution order is unchanged (streams carry the real dependencies).
    kpack<<<68, 256, 0, sB>>>(W1, W2);              // 1 (chain B)
    khist<<<HIST4_BLKS, 256>>>(dst);                // 2 (chain A)
    kscan_a<<<SCAN_BLKS, 256>>>();                  // 3 (chain A)
    k2_gemm1<<<(NN + G1M - 1) / G1M, 256, 0, sB>>>(x, a1s, a1d);  // 4 (chain B)
    kscan_b<<<1, 256>>>();                          // 5 (chain A)
    kscan_c<<<SCAN_BLKS, 256>>>();                  // 6 (chain A)
    k3_scatter<<<HIST4_BLKS, 256>>>(src, dst);      // 7 (chain A)

    // join
    cudaEventRecord(evJoin, sB);
    cudaStreamWaitEvent(0, evJoin, 0);

    // serial tail
    k4_agg1<<<(NN * 32 + 255) / 256, 256>>>();
    k4c_gemm2<<<(NN + G2_NB - 1) / G2_NB, 256>>>(a2s, a2d);
    k5_agg2<<<(NN * 32 + 255) / 256, 256>>>(out);
}